// round 1
// baseline (speedup 1.0000x reference)
#include <cuda_runtime.h>
#include <math.h>

#define SQ   2048
#define HID  2048
#define NH   16
#define HD   128
#define RD   64
#define DTOT 192   // HD + RD
#define KVC  512
#define QC   1024

// ---------------- scratch (device globals; no allocation allowed) ----------
__device__ float g_kv_c[SQ * KVC];
__device__ float g_q_c[SQ * QC];
__device__ float g_keys[NH * SQ * DTOT];     // [h][s][192]
__device__ float g_queries[NH * SQ * DTOT];  // [h][s][192], pre-scaled
__device__ float g_values[NH * SQ * HD];     // [h][s][128]
__device__ float g_ctx[SQ * NH * HD];        // [s][h*128]
__device__ float g_krw[NH * RD * KVC];       // rope-rotated key_rope_w
__device__ float g_qrw[NH * RD * QC];        // rope-rotated query_rope_w
__device__ float g_krb[NH * RD];
__device__ float g_qrb[NH * RD];

// ---------------- fold the (head-indexed!) rope rotation into weights ------
// Reference rope uses positions = arange(num_heads): angle = h * 10000^(-2i/64),
// independent of sequence position -> pure linear map on output channel pairs.
__global__ void rotate_w(const float* __restrict__ W, const float* __restrict__ b,
                         float* __restrict__ Wo, float* __restrict__ bo, int K)
{
    int pair = blockIdx.y;            // 0..NH*RD/2-1
    int h = pair >> 5;                // RD/2 = 32 pairs per head
    int i = pair & 31;
    float inv = powf(10000.0f, -(2.0f * (float)i) / 64.0f);
    float ang = (float)h * inv;
    float c = cosf(ang), s = sinf(ang);
    int c0 = pair * 2;
    int idx = blockIdx.x * 256 + threadIdx.x;
    if (idx < K) {
        float w1 = W[(size_t)c0 * K + idx];
        float w2 = W[(size_t)(c0 + 1) * K + idx];
        Wo[(size_t)c0 * K + idx]       = c * w1 - s * w2;
        Wo[(size_t)(c0 + 1) * K + idx] = s * w1 + c * w2;
    }
    if (idx == 0 && blockIdx.x == 0) {
        float b1 = b[c0], b2 = b[c0 + 1];
        bo[c0]     = c * b1 - s * b2;
        bo[c0 + 1] = s * b1 + c * b2;
    }
}

// ---------------- generic tiled GEMM: C = scale*(A @ W^T + bias) -----------
// A: [M,K] row-major; W: [N,K] row-major. Epilogue scatters by head:
//   dst = (col/head_sz)*head_stride + row*row_stride + col_off + col%head_sz
// M,N multiples of 64; K multiple of 16. 64x64 tile, 256 thr, 4x4 micro-tile.
__global__ __launch_bounds__(256) void gemm_bias(
    const float* __restrict__ A, const float* __restrict__ W,
    const float* __restrict__ bias, float* __restrict__ C,
    int K, int head_sz, int head_stride, int row_stride, int col_off,
    float scale)
{
    __shared__ float sA[64][17];
    __shared__ float sB[64][17];
    const int bm = blockIdx.y * 64, bn = blockIdx.x * 64;
    const int tid = threadIdx.x;
    const int ty = tid >> 4, tx = tid & 15;
    const int lr = tid >> 2, lc = (tid & 3) << 2;
    float acc[4][4] = {};
    const float* Ap = A + (size_t)(bm + lr) * K + lc;
    const float* Wp = W + (size_t)(bn + lr) * K + lc;

    for (int k0 = 0; k0 < K; k0 += 16) {
        float4 a4 = *(const float4*)(Ap + k0);
        float4 b4 = *(const float4*)(Wp + k0);
        sA[lr][lc] = a4.x; sA[lr][lc+1] = a4.y; sA[lr][lc+2] = a4.z; sA[lr][lc+3] = a4.w;
        sB[lr][lc] = b4.x; sB[lr][lc+1] = b4.y; sB[lr][lc+2] = b4.z; sB[lr][lc+3] = b4.w;
        __syncthreads();
        #pragma unroll
        for (int k = 0; k < 16; k++) {
            float a[4], b[4];
            #pragma unroll
            for (int i = 0; i < 4; i++) { a[i] = sA[ty*4+i][k]; b[i] = sB[tx*4+i][k]; }
            #pragma unroll
            for (int i = 0; i < 4; i++)
                #pragma unroll
                for (int j = 0; j < 4; j++)
                    acc[i][j] = fmaf(a[i], b[j], acc[i][j]);
        }
        __syncthreads();
    }

    #pragma unroll
    for (int i = 0; i < 4; i++) {
        int row = bm + ty * 4 + i;
        #pragma unroll
        for (int j = 0; j < 4; j++) {
            int col = bn + tx * 4 + j;
            float v = (acc[i][j] + bias[col]) * scale;
            size_t dst = (size_t)(col / head_sz) * head_stride
                       + (size_t)row * row_stride + col_off + (col % head_sz);
            C[dst] = v;
        }
    }
}

// ---------------- flash attention (non-causal, full softmax) ---------------
// Per block: one head, 64 queries. Stream 64-key tiles; online softmax.
__global__ __launch_bounds__(256) void attn(
    const float* __restrict__ Qg, const float* __restrict__ Kg,
    const float* __restrict__ Vg, float* __restrict__ Ctx)
{
    __shared__ float sA[64][17];
    __shared__ float sB[64][17];
    __shared__ float sP[64][65];
    __shared__ float sV[16][132];
    __shared__ float red[64][17];
    __shared__ float rowM[64], rowC[64], rowL[64];

    const int qb = blockIdx.x, h = blockIdx.y;
    const int tid = threadIdx.x;
    const int ty = tid >> 4, tx = tid & 15;
    const int lr = tid >> 2, lc = (tid & 3) << 2;
    const float* Qh = Qg + (size_t)h * SQ * DTOT + (size_t)qb * 64 * DTOT;
    const float* Kh = Kg + (size_t)h * SQ * DTOT;
    const float* Vh = Vg + (size_t)h * SQ * HD;

    float o[4][8] = {};
    if (tid < 64) { rowM[tid] = -INFINITY; rowL[tid] = 0.0f; }
    __syncthreads();

    for (int kb = 0; kb < SQ; kb += 64) {
        // ---- S = Q_tile @ K_tile^T  (64x64, K=192) ----
        float s[4][4] = {};
        for (int kc = 0; kc < DTOT; kc += 16) {
            float4 a4 = *(const float4*)(Qh + (size_t)lr * DTOT + kc + lc);
            float4 b4 = *(const float4*)(Kh + (size_t)(kb + lr) * DTOT + kc + lc);
            sA[lr][lc] = a4.x; sA[lr][lc+1] = a4.y; sA[lr][lc+2] = a4.z; sA[lr][lc+3] = a4.w;
            sB[lr][lc] = b4.x; sB[lr][lc+1] = b4.y; sB[lr][lc+2] = b4.z; sB[lr][lc+3] = b4.w;
            __syncthreads();
            #pragma unroll
            for (int k = 0; k < 16; k++) {
                float a[4], b[4];
                #pragma unroll
                for (int i = 0; i < 4; i++) { a[i] = sA[ty*4+i][k]; b[i] = sB[tx*4+i][k]; }
                #pragma unroll
                for (int i = 0; i < 4; i++)
                    #pragma unroll
                    for (int j = 0; j < 4; j++)
                        s[i][j] = fmaf(a[i], b[j], s[i][j]);
            }
            __syncthreads();
        }

        // ---- tile row-max ----
        #pragma unroll
        for (int i = 0; i < 4; i++) {
            float m = fmaxf(fmaxf(s[i][0], s[i][1]), fmaxf(s[i][2], s[i][3]));
            red[ty*4+i][tx] = m;
        }
        __syncthreads();
        if (tid < 64) {
            float m = red[tid][0];
            #pragma unroll
            for (int t = 1; t < 16; t++) m = fmaxf(m, red[tid][t]);
            float mo = rowM[tid];
            float mn = fmaxf(mo, m);
            rowM[tid] = mn;
            float c = __expf(mo - mn);
            rowC[tid] = c;
            rowL[tid] *= c;
        }
        __syncthreads();

        // ---- P = exp(S - m), partial row-sums, rescale O ----
        #pragma unroll
        for (int i = 0; i < 4; i++) {
            float mn = rowM[ty*4+i];
            float lsum = 0.0f;
            #pragma unroll
            for (int j = 0; j < 4; j++) {
                float p = __expf(s[i][j] - mn);
                sP[ty*4+i][tx*4+j] = p;
                lsum += p;
            }
            red[ty*4+i][tx] = lsum;
            float c = rowC[ty*4+i];
            #pragma unroll
            for (int j = 0; j < 8; j++) o[i][j] *= c;
        }
        __syncthreads();
        if (tid < 64) {
            float t = 0.0f;
            #pragma unroll
            for (int u = 0; u < 16; u++) t += red[tid][u];
            rowL[tid] += t;
        }

        // ---- O += P @ V_tile  (64x128, K=64) ----
        for (int kc = 0; kc < 64; kc += 16) {
            int vr = tid >> 4;           // 0..15
            int vc = (tid & 15) * 8;     // 0..120
            float4 v0 = *(const float4*)(Vh + (size_t)(kb + kc + vr) * HD + vc);
            float4 v1 = *(const float4*)(Vh + (size_t)(kb + kc + vr) * HD + vc + 4);
            *(float4*)&sV[vr][vc]     = v0;
            *(float4*)&sV[vr][vc + 4] = v1;
            __syncthreads();
            #pragma unroll
            for (int k = 0; k < 16; k++) {
                float a[4];
                #pragma unroll
                for (int i = 0; i < 4; i++) a[i] = sP[ty*4+i][kc + k];
                float4 b0 = *(const float4*)&sV[k][tx*8];
                float4 b1 = *(const float4*)&sV[k][tx*8 + 4];
                float b[8] = {b0.x, b0.y, b0.z, b0.w, b1.x, b1.y, b1.z, b1.w};
                #pragma unroll
                for (int i = 0; i < 4; i++)
                    #pragma unroll
                    for (int j = 0; j < 8; j++)
                        o[i][j] = fmaf(a[i], b[j], o[i][j]);
            }
            __syncthreads();
        }
    }

    // ---- finalize: ctx[s][h*128 + d] = O / l ----
    #pragma unroll
    for (int i = 0; i < 4; i++) {
        float inv = 1.0f / rowL[ty*4+i];
        int q = qb * 64 + ty * 4 + i;
        #pragma unroll
        for (int j = 0; j < 8; j++)
            Ctx[(size_t)q * (NH * HD) + h * HD + tx * 8 + j] = o[i][j] * inv;
    }
}

// ---------------- launch ---------------------------------------------------
extern "C" void kernel_launch(void* const* d_in, const int* in_sizes, int n_in,
                              void* d_out, int out_size)
{
    const float* x   = (const float*)d_in[0];
    const float* kdw = (const float*)d_in[1];
    const float* kdb = (const float*)d_in[2];
    const float* kuw = (const float*)d_in[3];
    const float* kub = (const float*)d_in[4];
    const float* vuw = (const float*)d_in[5];
    const float* vub = (const float*)d_in[6];
    const float* krw = (const float*)d_in[7];
    const float* krb = (const float*)d_in[8];
    const float* qdw = (const float*)d_in[9];
    const float* qdb = (const float*)d_in[10];
    const float* quw = (const float*)d_in[11];
    const float* qub = (const float*)d_in[12];
    const float* qrw = (const float*)d_in[13];
    const float* qrb = (const float*)d_in[14];
    const float* ow  = (const float*)d_in[15];
    const float* ob  = (const float*)d_in[16];
    float* out = (float*)d_out;

    float *p_kvc, *p_qc, *p_keys, *p_queries, *p_values, *p_ctx;
    float *p_krw, *p_qrw, *p_krb, *p_qrb;
    cudaGetSymbolAddress((void**)&p_kvc,     g_kv_c);
    cudaGetSymbolAddress((void**)&p_qc,      g_q_c);
    cudaGetSymbolAddress((void**)&p_keys,    g_keys);
    cudaGetSymbolAddress((void**)&p_queries, g_queries);
    cudaGetSymbolAddress((void**)&p_values,  g_values);
    cudaGetSymbolAddress((void**)&p_ctx,     g_ctx);
    cudaGetSymbolAddress((void**)&p_krw,     g_krw);
    cudaGetSymbolAddress((void**)&p_qrw,     g_qrw);
    cudaGetSymbolAddress((void**)&p_krb,     g_krb);
    cudaGetSymbolAddress((void**)&p_qrb,     g_qrb);

    const float scale = 1.0f / sqrtf((float)DTOT);
    dim3 blk(256);

    // fold rope rotation into rope weights (+biases)
    rotate_w<<<dim3((KVC + 255) / 256, NH * RD / 2), blk>>>(krw, krb, p_krw, p_krb, KVC);
    rotate_w<<<dim3((QC  + 255) / 256, NH * RD / 2), blk>>>(qrw, qrb, p_qrw, p_qrb, QC);

    // down projections
    gemm_bias<<<dim3(KVC / 64, SQ / 64), blk>>>(x, kdw, kdb, p_kvc, HID, KVC, 0, KVC, 0, 1.0f);
    gemm_bias<<<dim3(QC  / 64, SQ / 64), blk>>>(x, qdw, qdb, p_qc,  HID, QC,  0, QC,  0, 1.0f);

    // up projections, scattered into head-major [h][s][*] layouts
    gemm_bias<<<dim3(2048 / 64, SQ / 64), blk>>>(p_kvc, kuw,   kub,   p_keys,    KVC, HD, SQ*DTOT, DTOT, 0,   1.0f);
    gemm_bias<<<dim3(2048 / 64, SQ / 64), blk>>>(p_kvc, vuw,   vub,   p_values,  KVC, HD, SQ*HD,   HD,   0,   1.0f);
    gemm_bias<<<dim3(1024 / 64, SQ / 64), blk>>>(p_kvc, p_krw, p_krb, p_keys,    KVC, RD, SQ*DTOT, DTOT, HD,  1.0f);
    gemm_bias<<<dim3(2048 / 64, SQ / 64), blk>>>(p_qc,  quw,   qub,   p_queries, QC,  HD, SQ*DTOT, DTOT, 0,   scale);
    gemm_bias<<<dim3(1024 / 64, SQ / 64), blk>>>(p_qc,  p_qrw, p_qrb, p_queries, QC,  RD, SQ*DTOT, DTOT, HD,  scale);

    // attention -> ctx [s][h*128]
    attn<<<dim3(SQ / 64, NH), blk>>>(p_queries, p_keys, p_values, p_ctx);

    // output projection
    gemm_bias<<<dim3(2048 / 64, SQ / 64), blk>>>(p_ctx, ow, ob, out, 2048, 2048, 0, 2048, 0, 1.0f);
}

// round 2
// speedup vs baseline: 2.3085x; 2.3085x over previous
#include <cuda_runtime.h>
#include <math.h>

#define SQ   2048
#define HID  2048
#define NH   16
#define HD   128
#define RD   64
#define DTOT 192
#define KVC  512
#define QC   1024

// ---------------- scratch ---------------------------------------------------
__device__ float g_kv_c[SQ * KVC];
__device__ float g_q_c[SQ * QC];
__device__ float g_keys[NH * SQ * DTOT];
__device__ float g_queries[NH * SQ * DTOT];   // pre-scaled by 1/sqrt(192)
__device__ float g_values[NH * SQ * HD];
__device__ float g_ctx[SQ * NH * HD];
__device__ float g_krw[NH * RD * KVC];
__device__ float g_qrw[NH * RD * QC];
__device__ float g_krb[NH * RD];
__device__ float g_qrb[NH * RD];

// ---------------- fold head-indexed "rope" into weights ---------------------
__global__ void rotate_w(const float* __restrict__ W, const float* __restrict__ b,
                         float* __restrict__ Wo, float* __restrict__ bo, int K)
{
    int pair = blockIdx.y;
    int h = pair >> 5;
    int i = pair & 31;
    float inv = powf(10000.0f, -(2.0f * (float)i) / 64.0f);
    float ang = (float)h * inv;
    float c = cosf(ang), s = sinf(ang);
    int c0 = pair * 2;
    int idx = blockIdx.x * 256 + threadIdx.x;
    if (idx < K) {
        float w1 = W[(size_t)c0 * K + idx];
        float w2 = W[(size_t)(c0 + 1) * K + idx];
        Wo[(size_t)c0 * K + idx]       = c * w1 - s * w2;
        Wo[(size_t)(c0 + 1) * K + idx] = s * w1 + c * w2;
    }
    if (idx == 0 && blockIdx.x == 0) {
        float b1 = b[c0], b2 = b[c0 + 1];
        bo[c0]     = c * b1 - s * b2;
        bo[c0 + 1] = s * b1 + c * b2;
    }
}

// ---------------- 128x128 SGEMM, 8x8 micro-tile, double-buffered ------------
// C = scale*(A @ W^T + bias), head-scatter epilogue.
__global__ __launch_bounds__(256) void gemm128(
    const float* __restrict__ A, const float* __restrict__ W,
    const float* __restrict__ bias, float* __restrict__ C,
    int K, int head_sz, int head_stride, int row_stride, int col_off,
    float scale)
{
    __shared__ float sA[2][16][132];
    __shared__ float sB[2][16][132];
    const int bm = blockIdx.y * 128, bn = blockIdx.x * 128;
    const int tid = threadIdx.x;
    const int ty = tid >> 4, tx = tid & 15;
    const int r0 = tid >> 2;            // 0..63
    const int c0 = (tid & 3) << 2;      // 0,4,8,12

    const float* Ap  = A + (size_t)(bm + r0) * K + c0;
    const float* Ap2 = Ap + (size_t)64 * K;
    const float* Wp  = W + (size_t)(bn + r0) * K + c0;
    const float* Wp2 = Wp + (size_t)64 * K;

    float4 ra0 = *(const float4*)Ap;
    float4 ra1 = *(const float4*)Ap2;
    float4 rb0 = *(const float4*)Wp;
    float4 rb1 = *(const float4*)Wp2;

    float acc[8][8] = {};
    const int nk = K >> 4;

#define GSTORE(buf) do { \
    sA[buf][c0+0][r0]    = ra0.x; sA[buf][c0+1][r0]    = ra0.y; \
    sA[buf][c0+2][r0]    = ra0.z; sA[buf][c0+3][r0]    = ra0.w; \
    sA[buf][c0+0][r0+64] = ra1.x; sA[buf][c0+1][r0+64] = ra1.y; \
    sA[buf][c0+2][r0+64] = ra1.z; sA[buf][c0+3][r0+64] = ra1.w; \
    sB[buf][c0+0][r0]    = rb0.x; sB[buf][c0+1][r0]    = rb0.y; \
    sB[buf][c0+2][r0]    = rb0.z; sB[buf][c0+3][r0]    = rb0.w; \
    sB[buf][c0+0][r0+64] = rb1.x; sB[buf][c0+1][r0+64] = rb1.y; \
    sB[buf][c0+2][r0+64] = rb1.z; sB[buf][c0+3][r0+64] = rb1.w; \
} while (0)

    GSTORE(0);
    __syncthreads();

    for (int c = 0; c < nk; c++) {
        const int buf = c & 1;
        if (c + 1 < nk) {
            const int off = (c + 1) << 4;
            ra0 = *(const float4*)(Ap + off);
            ra1 = *(const float4*)(Ap2 + off);
            rb0 = *(const float4*)(Wp + off);
            rb1 = *(const float4*)(Wp2 + off);
        }
        #pragma unroll
        for (int k = 0; k < 16; k++) {
            float a[8], b[8];
            *(float4*)&a[0] = *(const float4*)&sA[buf][k][ty * 8];
            *(float4*)&a[4] = *(const float4*)&sA[buf][k][ty * 8 + 4];
            *(float4*)&b[0] = *(const float4*)&sB[buf][k][tx * 8];
            *(float4*)&b[4] = *(const float4*)&sB[buf][k][tx * 8 + 4];
            #pragma unroll
            for (int i = 0; i < 8; i++)
                #pragma unroll
                for (int j = 0; j < 8; j++)
                    acc[i][j] = fmaf(a[i], b[j], acc[i][j]);
        }
        if (c + 1 < nk) {
            GSTORE(buf ^ 1);
            __syncthreads();
        }
    }
#undef GSTORE

    // epilogue: head-scatter (cols tx*8..+7 never cross a head boundary)
    float bcol[8];
    #pragma unroll
    for (int j = 0; j < 8; j++) bcol[j] = bias[bn + tx * 8 + j];
    const int colbase = bn + tx * 8;
    const int dst0 = (colbase / head_sz) * head_stride + col_off + (colbase % head_sz);
    #pragma unroll
    for (int i = 0; i < 8; i++) {
        const size_t rowoff = (size_t)(bm + ty * 8 + i) * row_stride + dst0;
        float v[8];
        #pragma unroll
        for (int j = 0; j < 8; j++) v[j] = (acc[i][j] + bcol[j]) * scale;
        *(float4*)&C[rowoff]     = *(float4*)&v[0];
        *(float4*)&C[rowoff + 4] = *(float4*)&v[4];
    }
}

// ---------------- flash attention v2: 128q x 128k tiles, 8x8 micro ---------
#define SM_QT  0
#define SM_KT  (192 * 132)                 // [2][32][132]
#define SM_P   (SM_KT + 2 * 32 * 132)      // [128][132]
#define SM_V   (SM_P + 128 * 132)          // [32][132]
#define SM_RED (SM_V + 32 * 132)           // [128][17]
#define SM_RM  (SM_RED + 128 * 17)
#define SM_RC  (SM_RM + 128)
#define SM_RL  (SM_RC + 128)
#define ATTN_SMEM_FLOATS (SM_RL + 128)

__global__ __launch_bounds__(256) void attn2(
    const float* __restrict__ Qg, const float* __restrict__ Kg,
    const float* __restrict__ Vg, float* __restrict__ Ctx)
{
    extern __shared__ float sm[];
    float* sQt  = sm + SM_QT;
    float* sKt  = sm + SM_KT;
    float* sP   = sm + SM_P;
    float* sV   = sm + SM_V;
    float* red  = sm + SM_RED;
    float* rowM = sm + SM_RM;
    float* rowC = sm + SM_RC;
    float* rowL = sm + SM_RL;

    const int qb = blockIdx.x, h = blockIdx.y;
    const int tid = threadIdx.x;
    const int ty = tid >> 4, tx = tid & 15;
    const float* Qh = Qg + ((size_t)h * SQ + (size_t)qb * 128) * DTOT;
    const float* Kh = Kg + (size_t)h * SQ * DTOT;
    const float* Vh = Vg + (size_t)h * SQ * HD;

    // Q tile -> smem transposed [192][132], loaded ONCE per block
    #pragma unroll
    for (int i = 0; i < 24; i++) {
        int idx = tid + i * 256;          // 0..6143
        int row = idx / 48;
        int c4 = idx - row * 48;
        float4 q = *(const float4*)(Qh + (size_t)row * DTOT + c4 * 4);
        sQt[(c4 * 4 + 0) * 132 + row] = q.x;
        sQt[(c4 * 4 + 1) * 132 + row] = q.y;
        sQt[(c4 * 4 + 2) * 132 + row] = q.z;
        sQt[(c4 * 4 + 3) * 132 + row] = q.w;
    }
    if (tid < 128) { rowM[tid] = -INFINITY; rowL[tid] = 0.0f; }
    float o[8][8] = {};
    __syncthreads();

    const int krow = tid >> 3;            // 0..31
    const int kc4  = tid & 7;             // 0..7

    for (int kb = 0; kb < SQ; kb += 128) {
        const float* Kt = Kh + (size_t)kb * DTOT;
        float s[8][8] = {};
        float4 rk[4];

#define LOADK(kc) do { \
    rk[0] = *(const float4*)(Kt + (size_t)(krow)      * DTOT + (kc) + kc4 * 4); \
    rk[1] = *(const float4*)(Kt + (size_t)(krow + 32) * DTOT + (kc) + kc4 * 4); \
    rk[2] = *(const float4*)(Kt + (size_t)(krow + 64) * DTOT + (kc) + kc4 * 4); \
    rk[3] = *(const float4*)(Kt + (size_t)(krow + 96) * DTOT + (kc) + kc4 * 4); \
} while (0)
#define STOREK(buf) do { \
    float* p0 = &sKt[((buf) * 32 + kc4 * 4) * 132 + krow]; \
    float* p1 = p0 + 32, *p2 = p0 + 64, *p3 = p0 + 96; \
    p0[0] = rk[0].x; p0[132] = rk[0].y; p0[264] = rk[0].z; p0[396] = rk[0].w; \
    p1[0] = rk[1].x; p1[132] = rk[1].y; p1[264] = rk[1].z; p1[396] = rk[1].w; \
    p2[0] = rk[2].x; p2[132] = rk[2].y; p2[264] = rk[2].z; p2[396] = rk[2].w; \
    p3[0] = rk[3].x; p3[132] = rk[3].y; p3[264] = rk[3].z; p3[396] = rk[3].w; \
} while (0)

        LOADK(0);
        STOREK(0);
        __syncthreads();
        for (int c = 0; c < 6; c++) {
            const int buf = c & 1;
            if (c < 5) LOADK((c + 1) * 32);
            #pragma unroll
            for (int k = 0; k < 32; k++) {
                float a[8], b[8];
                const float* qa = &sQt[(c * 32 + k) * 132 + ty * 8];
                const float* kbp = &sKt[(buf * 32 + k) * 132 + tx * 8];
                *(float4*)&a[0] = *(const float4*)qa;
                *(float4*)&a[4] = *(const float4*)(qa + 4);
                *(float4*)&b[0] = *(const float4*)kbp;
                *(float4*)&b[4] = *(const float4*)(kbp + 4);
                #pragma unroll
                for (int i = 0; i < 8; i++)
                    #pragma unroll
                    for (int j = 0; j < 8; j++)
                        s[i][j] = fmaf(a[i], b[j], s[i][j]);
            }
            if (c < 5) {
                STOREK(buf ^ 1);
                __syncthreads();
            }
        }
#undef LOADK
#undef STOREK

        // row-max over this tile
        #pragma unroll
        for (int i = 0; i < 8; i++) {
            float m = s[i][0];
            #pragma unroll
            for (int j = 1; j < 8; j++) m = fmaxf(m, s[i][j]);
            red[(ty * 8 + i) * 17 + tx] = m;
        }
        __syncthreads();
        if (tid < 128) {
            float m = red[tid * 17];
            #pragma unroll
            for (int t = 1; t < 16; t++) m = fmaxf(m, red[tid * 17 + t]);
            float mo = rowM[tid];
            float mn = fmaxf(mo, m);
            rowM[tid] = mn;
            float cc = __expf(mo - mn);
            rowC[tid] = cc;
            rowL[tid] *= cc;
        }
        __syncthreads();

        // P = exp(S-m); partial sums; rescale O
        #pragma unroll
        for (int i = 0; i < 8; i++) {
            const int row = ty * 8 + i;
            const float mn = rowM[row];
            const float cc = rowC[row];
            float p[8];
            float ls = 0.0f;
            #pragma unroll
            for (int j = 0; j < 8; j++) { p[j] = __expf(s[i][j] - mn); ls += p[j]; }
            float* pp = &sP[row * 132 + tx * 8];
            *(float4*)pp       = *(float4*)&p[0];
            *(float4*)(pp + 4) = *(float4*)&p[4];
            red[row * 17 + tx] = ls;
            #pragma unroll
            for (int j = 0; j < 8; j++) o[i][j] *= cc;
        }
        __syncthreads();
        if (tid < 128) {
            float t = 0.0f;
            #pragma unroll
            for (int u = 0; u < 16; u++) t += red[tid * 17 + u];
            rowL[tid] += t;
        }

        // O += P @ V, streaming V in 32-row slices
        for (int vs = 0; vs < 4; vs++) {
            #pragma unroll
            for (int i = 0; i < 4; i++) {
                int idx = tid + i * 256;
                int vr = idx >> 5, vc = (idx & 31) * 4;
                *(float4*)&sV[vr * 132 + vc] =
                    *(const float4*)(Vh + (size_t)(kb + vs * 32 + vr) * HD + vc);
            }
            __syncthreads();
            #pragma unroll
            for (int k = 0; k < 32; k++) {
                float a[8], b[8];
                #pragma unroll
                for (int i = 0; i < 8; i++)
                    a[i] = sP[(ty * 8 + i) * 132 + vs * 32 + k];
                const float* vp = &sV[k * 132 + tx * 8];
                *(float4*)&b[0] = *(const float4*)vp;
                *(float4*)&b[4] = *(const float4*)(vp + 4);
                #pragma unroll
                for (int i = 0; i < 8; i++)
                    #pragma unroll
                    for (int j = 0; j < 8; j++)
                        o[i][j] = fmaf(a[i], b[j], o[i][j]);
            }
            __syncthreads();
        }
    }

    // finalize
    #pragma unroll
    for (int i = 0; i < 8; i++) {
        const int row = ty * 8 + i;
        const float inv = 1.0f / rowL[row];
        const int q = qb * 128 + row;
        float v[8];
        #pragma unroll
        for (int j = 0; j < 8; j++) v[j] = o[i][j] * inv;
        float* cp = &Ctx[(size_t)q * (NH * HD) + h * HD + tx * 8];
        *(float4*)cp       = *(float4*)&v[0];
        *(float4*)(cp + 4) = *(float4*)&v[4];
    }
}

// ---------------- launch ----------------------------------------------------
extern "C" void kernel_launch(void* const* d_in, const int* in_sizes, int n_in,
                              void* d_out, int out_size)
{
    const float* x   = (const float*)d_in[0];
    const float* kdw = (const float*)d_in[1];
    const float* kdb = (const float*)d_in[2];
    const float* kuw = (const float*)d_in[3];
    const float* kub = (const float*)d_in[4];
    const float* vuw = (const float*)d_in[5];
    const float* vub = (const float*)d_in[6];
    const float* krw = (const float*)d_in[7];
    const float* krb = (const float*)d_in[8];
    const float* qdw = (const float*)d_in[9];
    const float* qdb = (const float*)d_in[10];
    const float* quw = (const float*)d_in[11];
    const float* qub = (const float*)d_in[12];
    const float* qrw = (const float*)d_in[13];
    const float* qrb = (const float*)d_in[14];
    const float* ow  = (const float*)d_in[15];
    const float* ob  = (const float*)d_in[16];
    float* out = (float*)d_out;

    float *p_kvc, *p_qc, *p_keys, *p_queries, *p_values, *p_ctx;
    float *p_krw, *p_qrw, *p_krb, *p_qrb;
    cudaGetSymbolAddress((void**)&p_kvc,     g_kv_c);
    cudaGetSymbolAddress((void**)&p_qc,      g_q_c);
    cudaGetSymbolAddress((void**)&p_keys,    g_keys);
    cudaGetSymbolAddress((void**)&p_queries, g_queries);
    cudaGetSymbolAddress((void**)&p_values,  g_values);
    cudaGetSymbolAddress((void**)&p_ctx,     g_ctx);
    cudaGetSymbolAddress((void**)&p_krw,     g_krw);
    cudaGetSymbolAddress((void**)&p_qrw,     g_qrw);
    cudaGetSymbolAddress((void**)&p_krb,     g_krb);
    cudaGetSymbolAddress((void**)&p_qrb,     g_qrb);

    const float scale = 1.0f / sqrtf((float)DTOT);
    const size_t attn_smem = (size_t)ATTN_SMEM_FLOATS * sizeof(float);
    cudaFuncSetAttribute(attn2, cudaFuncAttributeMaxDynamicSharedMemorySize,
                         (int)attn_smem);
    dim3 blk(256);

    rotate_w<<<dim3((KVC + 255) / 256, NH * RD / 2), blk>>>(krw, krb, p_krw, p_krb, KVC);
    rotate_w<<<dim3((QC  + 255) / 256, NH * RD / 2), blk>>>(qrw, qrb, p_qrw, p_qrb, QC);

    // down projections
    gemm128<<<dim3(KVC / 128, SQ / 128), blk>>>(x, kdw, kdb, p_kvc, HID, KVC, 0, KVC, 0, 1.0f);
    gemm128<<<dim3(QC  / 128, SQ / 128), blk>>>(x, qdw, qdb, p_qc,  HID, QC,  0, QC,  0, 1.0f);

    // up projections -> head-major layouts
    gemm128<<<dim3(2048 / 128, SQ / 128), blk>>>(p_kvc, kuw,   kub,   p_keys,    KVC, HD, SQ*DTOT, DTOT, 0,  1.0f);
    gemm128<<<dim3(2048 / 128, SQ / 128), blk>>>(p_kvc, vuw,   vub,   p_values,  KVC, HD, SQ*HD,   HD,   0,  1.0f);
    gemm128<<<dim3(1024 / 128, SQ / 128), blk>>>(p_kvc, p_krw, p_krb, p_keys,    KVC, RD, SQ*DTOT, DTOT, HD, 1.0f);
    gemm128<<<dim3(2048 / 128, SQ / 128), blk>>>(p_qc,  quw,   qub,   p_queries, QC,  HD, SQ*DTOT, DTOT, 0,  scale);
    gemm128<<<dim3(1024 / 128, SQ / 128), blk>>>(p_qc,  p_qrw, p_qrb, p_queries, QC,  RD, SQ*DTOT, DTOT, HD, scale);

    // attention
    attn2<<<dim3(SQ / 128, NH), blk, attn_smem>>>(p_queries, p_keys, p_values, p_ctx);

    // output projection
    gemm128<<<dim3(2048 / 128, SQ / 128), blk>>>(p_ctx, ow, ob, out, 2048, 2048, 0, 2048, 0, 1.0f);
}

// round 4
// speedup vs baseline: 3.3001x; 1.4295x over previous
#include <cuda_runtime.h>
#include <cuda_bf16.h>
#include <math.h>
#include <stdint.h>

#define SQ   2048
#define HID  2048
#define NH   16
#define HD   128
#define RD   64
#define DTOT 192
#define KVC  512
#define QC   1024

// ---------------- scratch ---------------------------------------------------
__device__ float g_kv_c[SQ * KVC];
__device__ float g_q_c[SQ * QC];
__device__ float g_keys[NH * SQ * DTOT];
__device__ float g_queries[NH * SQ * DTOT];   // pre-scaled by 1/sqrt(192)
__device__ float g_values[NH * SQ * HD];
__device__ float g_ctx[SQ * NH * HD];
__device__ float g_krw[NH * RD * KVC];
__device__ float g_qrw[NH * RD * QC];
__device__ float g_krb[NH * RD];
__device__ float g_qrb[NH * RD];

// ---------------- fold head-indexed "rope" into weights ---------------------
__global__ void rotate_w(const float* __restrict__ W, const float* __restrict__ b,
                         float* __restrict__ Wo, float* __restrict__ bo, int K)
{
    int pair = blockIdx.y;
    int h = pair >> 5;
    int i = pair & 31;
    float inv = powf(10000.0f, -(2.0f * (float)i) / 64.0f);
    float ang = (float)h * inv;
    float c = cosf(ang), s = sinf(ang);
    int c0 = pair * 2;
    int idx = blockIdx.x * 256 + threadIdx.x;
    if (idx < K) {
        float w1 = W[(size_t)c0 * K + idx];
        float w2 = W[(size_t)(c0 + 1) * K + idx];
        Wo[(size_t)c0 * K + idx]       = c * w1 - s * w2;
        Wo[(size_t)(c0 + 1) * K + idx] = s * w1 + c * w2;
    }
    if (idx == 0 && blockIdx.x == 0) {
        float b1 = b[c0], b2 = b[c0 + 1];
        bo[c0]     = c * b1 - s * b2;
        bo[c0 + 1] = s * b1 + c * b2;
    }
}

// ---------------- mma.sync bf16 helper ---------------------------------------
__device__ __forceinline__ void mma_bf16(float* c, const uint32_t* a, const uint32_t* b)
{
    asm volatile(
        "mma.sync.aligned.m16n8k16.row.col.f32.bf16.bf16.f32 "
        "{%0,%1,%2,%3}, {%4,%5,%6,%7}, {%8,%9}, {%0,%1,%2,%3};"
        : "+f"(c[0]), "+f"(c[1]), "+f"(c[2]), "+f"(c[3])
        : "r"(a[0]), "r"(a[1]), "r"(a[2]), "r"(a[3]), "r"(b[0]), "r"(b[1]));
}

// ---------------- bf16-split tensor GEMM (mma.sync) --------------------------
// C = scale*(A @ W^T + bias). A:[M,K] fp32, W:[N,K] fp32.
// 128x128 block tile, 8 warps (4m x 2n), warp tile 32x64.
// hi/lo split, 3 passes: AhBh + AlBh + AhBl.
#define GS_STRIDE 72                      // bf16 units per smem row (144 B)
#define GS_TILE   (128 * GS_STRIDE)      // bf16 units per buffer
#define GT_SMEM   (4 * GS_TILE * 2)      // bytes = 73728

__global__ __launch_bounds__(256) void gemm_tc(
    const float* __restrict__ A, const float* __restrict__ W,
    const float* __restrict__ bias, float* __restrict__ C,
    int K, int head_sz, int head_stride, int row_stride, int col_off,
    float scale)
{
    extern __shared__ char smem[];
    char* AH = smem;
    char* AL = smem + GS_TILE * 2;
    char* BH = smem + GS_TILE * 4;
    char* BL = smem + GS_TILE * 6;

    const int tid = threadIdx.x;
    const int lane = tid & 31, wid = tid >> 5;
    const int g = lane >> 2, tig = lane & 3;
    const int wm = wid & 3, wn = wid >> 2;
    const int bm = blockIdx.y * 128, bn = blockIdx.x * 128;

    float acc[2][8][4] = {};

    const int nch = K >> 6;
    for (int ch = 0; ch < nch; ch++) {
        const int k0 = ch << 6;
        // ---- load fp32, split hi/lo bf16, store to smem ----
        #pragma unroll
        for (int i = 0; i < 8; i++) {
            int id = tid + (i << 8);
            int row = (id >> 3) & 127, cc = id & 7;
            const float* src;
            char *dh, *dl;
            if (id < 1024) { src = A + (size_t)(bm + row) * K + k0 + cc * 8; dh = AH; dl = AL; }
            else           { src = W + (size_t)(bn + row) * K + k0 + cc * 8; dh = BH; dl = BL; }
            float4 f0 = *(const float4*)src;
            float4 f1 = *(const float4*)(src + 4);
            float f[8] = {f0.x, f0.y, f0.z, f0.w, f1.x, f1.y, f1.z, f1.w};
            union { __nv_bfloat162 v[4]; uint4 u; } h, l;
            #pragma unroll
            for (int j = 0; j < 4; j++) {
                h.v[j] = __floats2bfloat162_rn(f[2*j], f[2*j+1]);
                float2 hf = __bfloat1622float2(h.v[j]);
                l.v[j] = __floats2bfloat162_rn(f[2*j] - hf.x, f[2*j+1] - hf.y);
            }
            uint32_t off = (uint32_t)(row * (GS_STRIDE * 2) + cc * 16);
            *(uint4*)(dh + off) = h.u;
            *(uint4*)(dl + off) = l.u;
        }
        __syncthreads();

        // ---- 4 k16 steps ----
        #pragma unroll
        for (int ks = 0; ks < 4; ks++) {
            const int kcb = ks * 32 + tig * 4;     // byte offset of k pair
            uint32_t ah[2][4], al[2][4], bh[8][2], bl[8][2];
            #pragma unroll
            for (int mt = 0; mt < 2; mt++) {
                const int r = wm * 32 + mt * 16 + g;
                const uint32_t o0 = (uint32_t)(r * (GS_STRIDE * 2)) + kcb;
                const uint32_t o1 = o0 + 8 * (GS_STRIDE * 2);
                ah[mt][0] = *(const uint32_t*)(AH + o0);
                ah[mt][1] = *(const uint32_t*)(AH + o1);
                ah[mt][2] = *(const uint32_t*)(AH + o0 + 16);
                ah[mt][3] = *(const uint32_t*)(AH + o1 + 16);
                al[mt][0] = *(const uint32_t*)(AL + o0);
                al[mt][1] = *(const uint32_t*)(AL + o1);
                al[mt][2] = *(const uint32_t*)(AL + o0 + 16);
                al[mt][3] = *(const uint32_t*)(AL + o1 + 16);
            }
            #pragma unroll
            for (int j = 0; j < 8; j++) {
                const int n = wn * 64 + j * 8 + g;
                const uint32_t o = (uint32_t)(n * (GS_STRIDE * 2)) + kcb;
                bh[j][0] = *(const uint32_t*)(BH + o);
                bh[j][1] = *(const uint32_t*)(BH + o + 16);
                bl[j][0] = *(const uint32_t*)(BL + o);
                bl[j][1] = *(const uint32_t*)(BL + o + 16);
            }
            #pragma unroll
            for (int mt = 0; mt < 2; mt++)
                #pragma unroll
                for (int j = 0; j < 8; j++) {
                    mma_bf16(acc[mt][j], ah[mt], bh[j]);
                    mma_bf16(acc[mt][j], al[mt], bh[j]);
                    mma_bf16(acc[mt][j], ah[mt], bl[j]);
                }
        }
        __syncthreads();
    }

    // ---- epilogue: registers -> global, head-scatter ----
    #pragma unroll
    for (int mt = 0; mt < 2; mt++) {
        const int row_lo = bm + wm * 32 + mt * 16 + g;
        const int row_hi = row_lo + 8;
        #pragma unroll
        for (int j = 0; j < 8; j++) {
            const int col = bn + wn * 64 + j * 8 + tig * 2;
            float2 bv = *(const float2*)(bias + col);
            const int dst0 = (col / head_sz) * head_stride + col_off + (col % head_sz);
            float2 v0 = make_float2((acc[mt][j][0] + bv.x) * scale,
                                    (acc[mt][j][1] + bv.y) * scale);
            float2 v1 = make_float2((acc[mt][j][2] + bv.x) * scale,
                                    (acc[mt][j][3] + bv.y) * scale);
            *(float2*)&C[(size_t)row_lo * row_stride + dst0] = v0;
            *(float2*)&C[(size_t)row_hi * row_stride + dst0] = v1;
        }
    }
}

// ---------------- flash attention v2 (fp32 SIMT) ----------------------------
#define SM_QT  0
#define SM_KT  (192 * 132)
#define SM_P   (SM_KT + 2 * 32 * 132)
#define SM_V   (SM_P + 128 * 132)
#define SM_RED (SM_V + 32 * 132)
#define SM_RM  (SM_RED + 128 * 17)
#define SM_RC  (SM_RM + 128)
#define SM_RL  (SM_RC + 128)
#define ATTN_SMEM_FLOATS (SM_RL + 128)

__global__ __launch_bounds__(256) void attn2(
    const float* __restrict__ Qg, const float* __restrict__ Kg,
    const float* __restrict__ Vg, float* __restrict__ Ctx)
{
    extern __shared__ float sm[];
    float* sQt  = sm + SM_QT;
    float* sKt  = sm + SM_KT;
    float* sP   = sm + SM_P;
    float* sV   = sm + SM_V;
    float* red  = sm + SM_RED;
    float* rowM = sm + SM_RM;
    float* rowC = sm + SM_RC;
    float* rowL = sm + SM_RL;

    const int qb = blockIdx.x, h = blockIdx.y;
    const int tid = threadIdx.x;
    const int ty = tid >> 4, tx = tid & 15;
    const float* Qh = Qg + ((size_t)h * SQ + (size_t)qb * 128) * DTOT;
    const float* Kh = Kg + (size_t)h * SQ * DTOT;
    const float* Vh = Vg + (size_t)h * SQ * HD;

    #pragma unroll
    for (int i = 0; i < 24; i++) {
        int idx = tid + i * 256;
        int row = idx / 48;
        int c4 = idx - row * 48;
        float4 q = *(const float4*)(Qh + (size_t)row * DTOT + c4 * 4);
        sQt[(c4 * 4 + 0) * 132 + row] = q.x;
        sQt[(c4 * 4 + 1) * 132 + row] = q.y;
        sQt[(c4 * 4 + 2) * 132 + row] = q.z;
        sQt[(c4 * 4 + 3) * 132 + row] = q.w;
    }
    if (tid < 128) { rowM[tid] = -INFINITY; rowL[tid] = 0.0f; }
    float o[8][8] = {};
    __syncthreads();

    const int krow = tid >> 3;
    const int kc4  = tid & 7;

    for (int kb = 0; kb < SQ; kb += 128) {
        const float* Kt = Kh + (size_t)kb * DTOT;
        float s[8][8] = {};
        float4 rk[4];

#define LOADK(kc) do { \
    rk[0] = *(const float4*)(Kt + (size_t)(krow)      * DTOT + (kc) + kc4 * 4); \
    rk[1] = *(const float4*)(Kt + (size_t)(krow + 32) * DTOT + (kc) + kc4 * 4); \
    rk[2] = *(const float4*)(Kt + (size_t)(krow + 64) * DTOT + (kc) + kc4 * 4); \
    rk[3] = *(const float4*)(Kt + (size_t)(krow + 96) * DTOT + (kc) + kc4 * 4); \
} while (0)
#define STOREK(buf) do { \
    float* p0 = &sKt[((buf) * 32 + kc4 * 4) * 132 + krow]; \
    float* p1 = p0 + 32, *p2 = p0 + 64, *p3 = p0 + 96; \
    p0[0] = rk[0].x; p0[132] = rk[0].y; p0[264] = rk[0].z; p0[396] = rk[0].w; \
    p1[0] = rk[1].x; p1[132] = rk[1].y; p1[264] = rk[1].z; p1[396] = rk[1].w; \
    p2[0] = rk[2].x; p2[132] = rk[2].y; p2[264] = rk[2].z; p2[396] = rk[2].w; \
    p3[0] = rk[3].x; p3[132] = rk[3].y; p3[264] = rk[3].z; p3[396] = rk[3].w; \
} while (0)

        LOADK(0);
        STOREK(0);
        __syncthreads();
        for (int c = 0; c < 6; c++) {
            const int buf = c & 1;
            if (c < 5) LOADK((c + 1) * 32);
            #pragma unroll
            for (int k = 0; k < 32; k++) {
                float a[8], b[8];
                const float* qa = &sQt[(c * 32 + k) * 132 + ty * 8];
                const float* kbp = &sKt[(buf * 32 + k) * 132 + tx * 8];
                *(float4*)&a[0] = *(const float4*)qa;
                *(float4*)&a[4] = *(const float4*)(qa + 4);
                *(float4*)&b[0] = *(const float4*)kbp;
                *(float4*)&b[4] = *(const float4*)(kbp + 4);
                #pragma unroll
                for (int i = 0; i < 8; i++)
                    #pragma unroll
                    for (int j = 0; j < 8; j++)
                        s[i][j] = fmaf(a[i], b[j], s[i][j]);
            }
            if (c < 5) {
                STOREK(buf ^ 1);
                __syncthreads();
            }
        }
#undef LOADK
#undef STOREK

        #pragma unroll
        for (int i = 0; i < 8; i++) {
            float m = s[i][0];
            #pragma unroll
            for (int j = 1; j < 8; j++) m = fmaxf(m, s[i][j]);
            red[(ty * 8 + i) * 17 + tx] = m;
        }
        __syncthreads();
        if (tid < 128) {
            float m = red[tid * 17];
            #pragma unroll
            for (int t = 1; t < 16; t++) m = fmaxf(m, red[tid * 17 + t]);
            float mo = rowM[tid];
            float mn = fmaxf(mo, m);
            rowM[tid] = mn;
            float cc = __expf(mo - mn);
            rowC[tid] = cc;
            rowL[tid] *= cc;
        }
        __syncthreads();

        #pragma unroll
        for (int i = 0; i < 8; i++) {
            const int row = ty * 8 + i;
            const float mn = rowM[row];
            const float cc = rowC[row];
            float p[8];
            float ls = 0.0f;
            #pragma unroll
            for (int j = 0; j < 8; j++) { p[j] = __expf(s[i][j] - mn); ls += p[j]; }
            float* pp = &sP[row * 132 + tx * 8];
            *(float4*)pp       = *(float4*)&p[0];
            *(float4*)(pp + 4) = *(float4*)&p[4];
            red[row * 17 + tx] = ls;
            #pragma unroll
            for (int j = 0; j < 8; j++) o[i][j] *= cc;
        }
        __syncthreads();
        if (tid < 128) {
            float t = 0.0f;
            #pragma unroll
            for (int u = 0; u < 16; u++) t += red[tid * 17 + u];
            rowL[tid] += t;
        }

        for (int vs = 0; vs < 4; vs++) {
            #pragma unroll
            for (int i = 0; i < 4; i++) {
                int idx = tid + i * 256;
                int vr = idx >> 5, vc = (idx & 31) * 4;
                *(float4*)&sV[vr * 132 + vc] =
                    *(const float4*)(Vh + (size_t)(kb + vs * 32 + vr) * HD + vc);
            }
            __syncthreads();
            #pragma unroll
            for (int k = 0; k < 32; k++) {
                float a[8], b[8];
                #pragma unroll
                for (int i = 0; i < 8; i++)
                    a[i] = sP[(ty * 8 + i) * 132 + vs * 32 + k];
                const float* vp = &sV[k * 132 + tx * 8];
                *(float4*)&b[0] = *(const float4*)vp;
                *(float4*)&b[4] = *(const float4*)(vp + 4);
                #pragma unroll
                for (int i = 0; i < 8; i++)
                    #pragma unroll
                    for (int j = 0; j < 8; j++)
                        o[i][j] = fmaf(a[i], b[j], o[i][j]);
            }
            __syncthreads();
        }
    }

    #pragma unroll
    for (int i = 0; i < 8; i++) {
        const int row = ty * 8 + i;
        const float inv = 1.0f / rowL[row];
        const int q = qb * 128 + row;
        float v[8];
        #pragma unroll
        for (int j = 0; j < 8; j++) v[j] = o[i][j] * inv;
        float* cp = &Ctx[(size_t)q * (NH * HD) + h * HD + tx * 8];
        *(float4*)cp       = *(float4*)&v[0];
        *(float4*)(cp + 4) = *(float4*)&v[4];
    }
}

// ---------------- launch ----------------------------------------------------
extern "C" void kernel_launch(void* const* d_in, const int* in_sizes, int n_in,
                              void* d_out, int out_size)
{
    const float* x   = (const float*)d_in[0];
    const float* kdw = (const float*)d_in[1];
    const float* kdb = (const float*)d_in[2];
    const float* kuw = (const float*)d_in[3];
    const float* kub = (const float*)d_in[4];
    const float* vuw = (const float*)d_in[5];
    const float* vub = (const float*)d_in[6];
    const float* krw = (const float*)d_in[7];
    const float* krb = (const float*)d_in[8];
    const float* qdw = (const float*)d_in[9];
    const float* qdb = (const float*)d_in[10];
    const float* quw = (const float*)d_in[11];
    const float* qub = (const float*)d_in[12];
    const float* qrw = (const float*)d_in[13];
    const float* qrb = (const float*)d_in[14];
    const float* ow  = (const float*)d_in[15];
    const float* ob  = (const float*)d_in[16];
    float* out = (float*)d_out;

    float *p_kvc, *p_qc, *p_keys, *p_queries, *p_values, *p_ctx;
    float *p_krw, *p_qrw, *p_krb, *p_qrb;
    cudaGetSymbolAddress((void**)&p_kvc,     g_kv_c);
    cudaGetSymbolAddress((void**)&p_qc,      g_q_c);
    cudaGetSymbolAddress((void**)&p_keys,    g_keys);
    cudaGetSymbolAddress((void**)&p_queries, g_queries);
    cudaGetSymbolAddress((void**)&p_values,  g_values);
    cudaGetSymbolAddress((void**)&p_ctx,     g_ctx);
    cudaGetSymbolAddress((void**)&p_krw,     g_krw);
    cudaGetSymbolAddress((void**)&p_qrw,     g_qrw);
    cudaGetSymbolAddress((void**)&p_krb,     g_krb);
    cudaGetSymbolAddress((void**)&p_qrb,     g_qrb);

    const float scale = 1.0f / sqrtf((float)DTOT);
    const size_t attn_smem = (size_t)ATTN_SMEM_FLOATS * sizeof(float);
    cudaFuncSetAttribute(attn2, cudaFuncAttributeMaxDynamicSharedMemorySize,
                         (int)attn_smem);
    cudaFuncSetAttribute(gemm_tc, cudaFuncAttributeMaxDynamicSharedMemorySize,
                         GT_SMEM);
    dim3 blk(256);

    rotate_w<<<dim3((KVC + 255) / 256, NH * RD / 2), blk>>>(krw, krb, p_krw, p_krb, KVC);
    rotate_w<<<dim3((QC  + 255) / 256, NH * RD / 2), blk>>>(qrw, qrb, p_qrw, p_qrb, QC);

    // down projections
    gemm_tc<<<dim3(KVC / 128, SQ / 128), blk, GT_SMEM>>>(x, kdw, kdb, p_kvc, HID, KVC, 0, KVC, 0, 1.0f);
    gemm_tc<<<dim3(QC  / 128, SQ / 128), blk, GT_SMEM>>>(x, qdw, qdb, p_qc,  HID, QC,  0, QC,  0, 1.0f);

    // up projections -> head-major layouts
    gemm_tc<<<dim3(2048 / 128, SQ / 128), blk, GT_SMEM>>>(p_kvc, kuw,   kub,   p_keys,    KVC, HD, SQ*DTOT, DTOT, 0,  1.0f);
    gemm_tc<<<dim3(2048 / 128, SQ / 128), blk, GT_SMEM>>>(p_kvc, vuw,   vub,   p_values,  KVC, HD, SQ*HD,   HD,   0,  1.0f);
    gemm_tc<<<dim3(1024 / 128, SQ / 128), blk, GT_SMEM>>>(p_kvc, p_krw, p_krb, p_keys,    KVC, RD, SQ*DTOT, DTOT, HD, 1.0f);
    gemm_tc<<<dim3(2048 / 128, SQ / 128), blk, GT_SMEM>>>(p_qc,  quw,   qub,   p_queries, QC,  HD, SQ*DTOT, DTOT, 0,  scale);
    gemm_tc<<<dim3(1024 / 128, SQ / 128), blk, GT_SMEM>>>(p_qc,  p_qrw, p_qrb, p_queries, QC,  RD, SQ*DTOT, DTOT, HD, scale);

    // attention
    attn2<<<dim3(SQ / 128, NH), blk, attn_smem>>>(p_queries, p_keys, p_values, p_ctx);

    // output projection
    gemm_tc<<<dim3(2048 / 128, SQ / 128), blk, GT_SMEM>>>(p_ctx, ow, ob, out, 2048, 2048, 0, 2048, 0, 1.0f);
}

// round 5
// speedup vs baseline: 4.7903x; 1.4516x over previous
#include <cuda_runtime.h>
#include <cuda_bf16.h>
#include <math.h>
#include <stdint.h>

#define SQ   2048
#define HID  2048
#define NH   16
#define HD   128
#define RD   64
#define DTOT 192
#define KVC  512
#define QC   1024

// ---------------- scratch ---------------------------------------------------
__device__ float g_kv_c[SQ * KVC];
__device__ float g_q_c[SQ * QC];
__device__ float g_ctx[SQ * NH * HD];
__device__ float g_krw[NH * RD * KVC];
__device__ float g_qrw[NH * RD * QC];
__device__ float g_krb[NH * RD];
__device__ float g_qrb[NH * RD];
__device__ __nv_bfloat16 g_qh[NH * SQ * DTOT];   // queries bf16 (pre-scaled)
__device__ __nv_bfloat16 g_kh[NH * SQ * DTOT];   // keys bf16
__device__ __nv_bfloat16 g_vth[NH * HD * SQ];    // values hi, transposed [h][d][s]
__device__ __nv_bfloat16 g_vtl[NH * HD * SQ];    // values lo

// ---------------- fold head-indexed "rope" into weights ---------------------
__global__ void rotate_w(const float* __restrict__ W, const float* __restrict__ b,
                         float* __restrict__ Wo, float* __restrict__ bo, int K)
{
    int pair = blockIdx.y;
    int h = pair >> 5;
    int i = pair & 31;
    float inv = powf(10000.0f, -(2.0f * (float)i) / 64.0f);
    float ang = (float)h * inv;
    float c = cosf(ang), s = sinf(ang);
    int c0 = pair * 2;
    int idx = blockIdx.x * 256 + threadIdx.x;
    if (idx < K) {
        float w1 = W[(size_t)c0 * K + idx];
        float w2 = W[(size_t)(c0 + 1) * K + idx];
        Wo[(size_t)c0 * K + idx]       = c * w1 - s * w2;
        Wo[(size_t)(c0 + 1) * K + idx] = s * w1 + c * w2;
    }
    if (idx == 0 && blockIdx.x == 0) {
        float b1 = b[c0], b2 = b[c0 + 1];
        bo[c0]     = c * b1 - s * b2;
        bo[c0 + 1] = s * b1 + c * b2;
    }
}

// ---------------- mma.sync bf16 helper ---------------------------------------
__device__ __forceinline__ void mma_bf16(float* c, const uint32_t* a, const uint32_t* b)
{
    asm volatile(
        "mma.sync.aligned.m16n8k16.row.col.f32.bf16.bf16.f32 "
        "{%0,%1,%2,%3}, {%4,%5,%6,%7}, {%8,%9}, {%0,%1,%2,%3};"
        : "+f"(c[0]), "+f"(c[1]), "+f"(c[2]), "+f"(c[3])
        : "r"(a[0]), "r"(a[1]), "r"(a[2]), "r"(a[3]), "r"(b[0]), "r"(b[1]));
}

// ---------------- bf16-split tensor GEMM (mma.sync) --------------------------
// C = scale*(A @ W^T + bias). 128x128 tile, 8 warps (4m x 2n), warp 32x64.
// mode 0: fp32 out, head-scatter.  mode 1: bf16 out, head-scatter.
// mode 2: bf16 hi/lo out, transposed [head][d][s] (for values).
#define GS_STRIDE 72
#define GS_TILE   (128 * GS_STRIDE)
#define GT_SMEM   (4 * GS_TILE * 2)      // 73728 bytes

__global__ __launch_bounds__(256) void gemm_tc(
    const float* __restrict__ A, const float* __restrict__ W,
    const float* __restrict__ bias,
    float* __restrict__ C, __nv_bfloat16* __restrict__ Cb,
    __nv_bfloat16* __restrict__ Cb2,
    int K, int head_sz, int head_stride, int row_stride, int col_off,
    float scale, int mode)
{
    extern __shared__ char smem[];
    char* AH = smem;
    char* AL = smem + GS_TILE * 2;
    char* BH = smem + GS_TILE * 4;
    char* BL = smem + GS_TILE * 6;

    const int tid = threadIdx.x;
    const int lane = tid & 31, wid = tid >> 5;
    const int g = lane >> 2, tig = lane & 3;
    const int wm = wid & 3, wn = wid >> 2;
    const int bm = blockIdx.y * 128, bn = blockIdx.x * 128;

    float acc[2][8][4] = {};

    const int nch = K >> 6;
    for (int ch = 0; ch < nch; ch++) {
        const int k0 = ch << 6;
        #pragma unroll
        for (int i = 0; i < 8; i++) {
            int id = tid + (i << 8);
            int row = (id >> 3) & 127, cc = id & 7;
            const float* src;
            char *dh, *dl;
            if (id < 1024) { src = A + (size_t)(bm + row) * K + k0 + cc * 8; dh = AH; dl = AL; }
            else           { src = W + (size_t)(bn + row) * K + k0 + cc * 8; dh = BH; dl = BL; }
            float4 f0 = *(const float4*)src;
            float4 f1 = *(const float4*)(src + 4);
            float f[8] = {f0.x, f0.y, f0.z, f0.w, f1.x, f1.y, f1.z, f1.w};
            union { __nv_bfloat162 v[4]; uint4 u; } h, l;
            #pragma unroll
            for (int j = 0; j < 4; j++) {
                h.v[j] = __floats2bfloat162_rn(f[2*j], f[2*j+1]);
                float2 hf = __bfloat1622float2(h.v[j]);
                l.v[j] = __floats2bfloat162_rn(f[2*j] - hf.x, f[2*j+1] - hf.y);
            }
            uint32_t off = (uint32_t)(row * (GS_STRIDE * 2) + cc * 16);
            *(uint4*)(dh + off) = h.u;
            *(uint4*)(dl + off) = l.u;
        }
        __syncthreads();

        #pragma unroll
        for (int ks = 0; ks < 4; ks++) {
            const int kcb = ks * 32 + tig * 4;
            uint32_t ah[2][4], al[2][4], bh[8][2], bl[8][2];
            #pragma unroll
            for (int mt = 0; mt < 2; mt++) {
                const int r = wm * 32 + mt * 16 + g;
                const uint32_t o0 = (uint32_t)(r * (GS_STRIDE * 2)) + kcb;
                const uint32_t o1 = o0 + 8 * (GS_STRIDE * 2);
                ah[mt][0] = *(const uint32_t*)(AH + o0);
                ah[mt][1] = *(const uint32_t*)(AH + o1);
                ah[mt][2] = *(const uint32_t*)(AH + o0 + 16);
                ah[mt][3] = *(const uint32_t*)(AH + o1 + 16);
                al[mt][0] = *(const uint32_t*)(AL + o0);
                al[mt][1] = *(const uint32_t*)(AL + o1);
                al[mt][2] = *(const uint32_t*)(AL + o0 + 16);
                al[mt][3] = *(const uint32_t*)(AL + o1 + 16);
            }
            #pragma unroll
            for (int j = 0; j < 8; j++) {
                const int n = wn * 64 + j * 8 + g;
                const uint32_t o = (uint32_t)(n * (GS_STRIDE * 2)) + kcb;
                bh[j][0] = *(const uint32_t*)(BH + o);
                bh[j][1] = *(const uint32_t*)(BH + o + 16);
                bl[j][0] = *(const uint32_t*)(BL + o);
                bl[j][1] = *(const uint32_t*)(BL + o + 16);
            }
            #pragma unroll
            for (int mt = 0; mt < 2; mt++)
                #pragma unroll
                for (int j = 0; j < 8; j++) {
                    mma_bf16(acc[mt][j], ah[mt], bh[j]);
                    mma_bf16(acc[mt][j], al[mt], bh[j]);
                    mma_bf16(acc[mt][j], ah[mt], bl[j]);
                }
        }
        __syncthreads();
    }

    if (mode == 0) {
        #pragma unroll
        for (int mt = 0; mt < 2; mt++) {
            const int row_lo = bm + wm * 32 + mt * 16 + g;
            const int row_hi = row_lo + 8;
            #pragma unroll
            for (int j = 0; j < 8; j++) {
                const int col = bn + wn * 64 + j * 8 + tig * 2;
                float2 bv = *(const float2*)(bias + col);
                const int dst0 = (col / head_sz) * head_stride + col_off + (col % head_sz);
                float2 v0 = make_float2((acc[mt][j][0] + bv.x) * scale,
                                        (acc[mt][j][1] + bv.y) * scale);
                float2 v1 = make_float2((acc[mt][j][2] + bv.x) * scale,
                                        (acc[mt][j][3] + bv.y) * scale);
                *(float2*)&C[(size_t)row_lo * row_stride + dst0] = v0;
                *(float2*)&C[(size_t)row_hi * row_stride + dst0] = v1;
            }
        }
    } else if (mode == 1) {
        #pragma unroll
        for (int mt = 0; mt < 2; mt++) {
            const int row_lo = bm + wm * 32 + mt * 16 + g;
            const int row_hi = row_lo + 8;
            #pragma unroll
            for (int j = 0; j < 8; j++) {
                const int col = bn + wn * 64 + j * 8 + tig * 2;
                float2 bv = *(const float2*)(bias + col);
                const int dst0 = (col / head_sz) * head_stride + col_off + (col % head_sz);
                __nv_bfloat162 v0 = __floats2bfloat162_rn((acc[mt][j][0] + bv.x) * scale,
                                                          (acc[mt][j][1] + bv.y) * scale);
                __nv_bfloat162 v1 = __floats2bfloat162_rn((acc[mt][j][2] + bv.x) * scale,
                                                          (acc[mt][j][3] + bv.y) * scale);
                *(__nv_bfloat162*)&Cb[(size_t)row_lo * row_stride + dst0] = v0;
                *(__nv_bfloat162*)&Cb[(size_t)row_hi * row_stride + dst0] = v1;
            }
        }
    } else {
        // mode 2: stage fp32 tile -> smem, transpose -> bf16 hi/lo [head][d][s]
        float* ep = (float*)smem;
        #pragma unroll
        for (int mt = 0; mt < 2; mt++) {
            const int r0 = wm * 32 + mt * 16 + g;
            #pragma unroll
            for (int j = 0; j < 8; j++) {
                const int cl = wn * 64 + j * 8 + tig * 2;
                *(float2*)&ep[r0 * 132 + cl]       = make_float2(acc[mt][j][0], acc[mt][j][1]);
                *(float2*)&ep[(r0 + 8) * 132 + cl] = make_float2(acc[mt][j][2], acc[mt][j][3]);
            }
        }
        __syncthreads();
        const int d = tid >> 1, sh = tid & 1;
        const int head = bn >> 7;
        const float bv = bias[bn + d];
        #pragma unroll
        for (int s8 = 0; s8 < 8; s8++) {
            const int sl = sh * 64 + s8 * 8;
            union { __nv_bfloat16 b[8]; uint4 u; } hh, ll;
            #pragma unroll
            for (int u = 0; u < 8; u++) {
                float v = (ep[(sl + u) * 132 + d] + bv) * scale;
                hh.b[u] = __float2bfloat16(v);
                ll.b[u] = __float2bfloat16(v - __bfloat162float(hh.b[u]));
            }
            size_t base = ((size_t)head * HD + d) * SQ + bm + sl;
            *(uint4*)&Cb[base]  = hh.u;
            *(uint4*)&Cb2[base] = ll.u;
        }
    }
}

// ---------------- tensor-core flash attention --------------------------------
// grid (16 qb, 16 h), 256 thr, 8 warps (4m x 2n). 128q x 128k tiles.
// QK single-pass bf16; PV 3-pass (Ph Vh + Pl Vh + Ph Vl).
#define QSTR 200
#define KSTR 72
#define PSTR 136
#define VSTR 72
#define AS_Q    0
#define AS_K    (AS_Q + 128 * QSTR * 2)
#define AS_PH   (AS_K + 128 * KSTR * 2)
#define AS_PL   (AS_PH + 128 * PSTR * 2)
#define AS_VH   (AS_PL + 128 * PSTR * 2)
#define AS_VL   (AS_VH + 128 * VSTR * 2)
#define AS_REDM (AS_VL + 128 * VSTR * 2)
#define AS_REDL (AS_REDM + 128 * 2 * 4)
#define AS_ROWM (AS_REDL + 128 * 2 * 4)
#define AS_ROWC (AS_ROWM + 128 * 4)
#define AS_ROWL (AS_ROWC + 128 * 4)
#define ATTN_SMEM (AS_ROWL + 128 * 4)

__device__ __forceinline__ float expapx(float x)
{
    if (x > -0.0625f)
        return 1.0f + x * (1.0f + x * (0.5f + x * 0.16666667f));
    return __expf(x);
}

__global__ __launch_bounds__(256) void attn3(
    const __nv_bfloat16* __restrict__ Qg, const __nv_bfloat16* __restrict__ Kg,
    const __nv_bfloat16* __restrict__ VTh, const __nv_bfloat16* __restrict__ VTl,
    float* __restrict__ Ctx)
{
    extern __shared__ char sm[];
    char* sQ  = sm + AS_Q;
    char* sK  = sm + AS_K;
    char* sPh = sm + AS_PH;
    char* sPl = sm + AS_PL;
    char* sVh = sm + AS_VH;
    char* sVl = sm + AS_VL;
    float* redM = (float*)(sm + AS_REDM);
    float* redL = (float*)(sm + AS_REDL);
    float* rowM = (float*)(sm + AS_ROWM);
    float* rowC = (float*)(sm + AS_ROWC);
    float* rowL = (float*)(sm + AS_ROWL);

    const int qb = blockIdx.x, h = blockIdx.y;
    const int tid = threadIdx.x;
    const int lane = tid & 31, wid = tid >> 5;
    const int g = lane >> 2, tig = lane & 3;
    const int wm = wid & 3, wn = wid >> 2;

    const __nv_bfloat16* Qh = Qg + ((size_t)h * SQ + qb * 128) * DTOT;
    const __nv_bfloat16* Kh = Kg + (size_t)h * SQ * DTOT;

    #pragma unroll
    for (int i = 0; i < 12; i++) {
        int id = tid + i * 256;
        int r = id / 24, c8 = id % 24;
        *(uint4*)(sQ + r * (QSTR * 2) + c8 * 16) =
            *(const uint4*)(Qh + (size_t)r * DTOT + c8 * 8);
    }
    if (tid < 128) { rowM[tid] = -INFINITY; rowL[tid] = 0.0f; }

    float O[2][8][4] = {};
    __syncthreads();

    for (int kb = 0; kb < SQ / 128; kb++) {
        // ---- S = Q K^T ----
        float S[2][8][4] = {};
        for (int kc = 0; kc < 3; kc++) {
            #pragma unroll
            for (int i = 0; i < 4; i++) {
                int id = tid + i * 256;
                int r = id >> 3, c8 = id & 7;
                *(uint4*)(sK + r * (KSTR * 2) + c8 * 16) =
                    *(const uint4*)(Kh + (size_t)(kb * 128 + r) * DTOT + kc * 64 + c8 * 8);
            }
            __syncthreads();
            #pragma unroll
            for (int ks = 0; ks < 4; ks++) {
                uint32_t a[2][4], b[8][2];
                const int kby = (kc * 64 + ks * 16 + tig * 2) * 2;
                #pragma unroll
                for (int mt = 0; mt < 2; mt++) {
                    const char* p0 = sQ + (wm * 32 + mt * 16 + g) * (QSTR * 2) + kby;
                    a[mt][0] = *(const uint32_t*)p0;
                    a[mt][1] = *(const uint32_t*)(p0 + 8 * (QSTR * 2));
                    a[mt][2] = *(const uint32_t*)(p0 + 16);
                    a[mt][3] = *(const uint32_t*)(p0 + 8 * (QSTR * 2) + 16);
                }
                const int kby2 = (ks * 16 + tig * 2) * 2;
                #pragma unroll
                for (int j = 0; j < 8; j++) {
                    const char* p = sK + (wn * 64 + j * 8 + g) * (KSTR * 2) + kby2;
                    b[j][0] = *(const uint32_t*)p;
                    b[j][1] = *(const uint32_t*)(p + 16);
                }
                #pragma unroll
                for (int mt = 0; mt < 2; mt++)
                    #pragma unroll
                    for (int j = 0; j < 8; j++)
                        mma_bf16(S[mt][j], a[mt], b[j]);
            }
            __syncthreads();
        }

        // ---- softmax ----
        #pragma unroll
        for (int mt = 0; mt < 2; mt++) {
            float m0 = -INFINITY, m1 = -INFINITY;
            #pragma unroll
            for (int j = 0; j < 8; j++) {
                m0 = fmaxf(m0, fmaxf(S[mt][j][0], S[mt][j][1]));
                m1 = fmaxf(m1, fmaxf(S[mt][j][2], S[mt][j][3]));
            }
            m0 = fmaxf(m0, __shfl_xor_sync(~0u, m0, 1));
            m0 = fmaxf(m0, __shfl_xor_sync(~0u, m0, 2));
            m1 = fmaxf(m1, __shfl_xor_sync(~0u, m1, 1));
            m1 = fmaxf(m1, __shfl_xor_sync(~0u, m1, 2));
            if (tig == 0) {
                redM[(wm * 32 + mt * 16 + g) * 2 + wn] = m0;
                redM[(wm * 32 + mt * 16 + g + 8) * 2 + wn] = m1;
            }
        }
        __syncthreads();
        if (wn == 0 && tig == 0) {
            #pragma unroll
            for (int mt = 0; mt < 2; mt++)
                #pragma unroll
                for (int hf = 0; hf < 2; hf++) {
                    int r = wm * 32 + mt * 16 + hf * 8 + g;
                    float tm = fmaxf(redM[r * 2], redM[r * 2 + 1]);
                    float mo = rowM[r];
                    float mn = fmaxf(mo, tm);
                    rowM[r] = mn;
                    rowC[r] = __expf(mo - mn);
                }
        }
        __syncthreads();

        #pragma unroll
        for (int mt = 0; mt < 2; mt++) {
            const int r0 = wm * 32 + mt * 16 + g, r1 = r0 + 8;
            const float mn0 = rowM[r0], mn1 = rowM[r1];
            const float c0 = rowC[r0], c1 = rowC[r1];
            float s0 = 0.0f, s1 = 0.0f;
            #pragma unroll
            for (int j = 0; j < 8; j++) {
                const int col = wn * 64 + j * 8 + tig * 2;
                float p00 = expapx(S[mt][j][0] - mn0);
                float p01 = expapx(S[mt][j][1] - mn0);
                float p10 = expapx(S[mt][j][2] - mn1);
                float p11 = expapx(S[mt][j][3] - mn1);
                s0 += p00 + p01;
                s1 += p10 + p11;
                __nv_bfloat162 h0 = __floats2bfloat162_rn(p00, p01);
                float2 hf0 = __bfloat1622float2(h0);
                __nv_bfloat162 l0 = __floats2bfloat162_rn(p00 - hf0.x, p01 - hf0.y);
                __nv_bfloat162 h1 = __floats2bfloat162_rn(p10, p11);
                float2 hf1 = __bfloat1622float2(h1);
                __nv_bfloat162 l1 = __floats2bfloat162_rn(p10 - hf1.x, p11 - hf1.y);
                *(__nv_bfloat162*)(sPh + r0 * (PSTR * 2) + col * 2) = h0;
                *(__nv_bfloat162*)(sPl + r0 * (PSTR * 2) + col * 2) = l0;
                *(__nv_bfloat162*)(sPh + r1 * (PSTR * 2) + col * 2) = h1;
                *(__nv_bfloat162*)(sPl + r1 * (PSTR * 2) + col * 2) = l1;
                O[mt][j][0] *= c0; O[mt][j][1] *= c0;
                O[mt][j][2] *= c1; O[mt][j][3] *= c1;
            }
            s0 += __shfl_xor_sync(~0u, s0, 1);
            s0 += __shfl_xor_sync(~0u, s0, 2);
            s1 += __shfl_xor_sync(~0u, s1, 1);
            s1 += __shfl_xor_sync(~0u, s1, 2);
            if (tig == 0) { redL[r0 * 2 + wn] = s0; redL[r1 * 2 + wn] = s1; }
        }
        __syncthreads();
        if (wn == 0 && tig == 0) {
            #pragma unroll
            for (int mt = 0; mt < 2; mt++)
                #pragma unroll
                for (int hf = 0; hf < 2; hf++) {
                    int r = wm * 32 + mt * 16 + hf * 8 + g;
                    rowL[r] = rowL[r] * rowC[r] + redL[r * 2] + redL[r * 2 + 1];
                }
        }

        // ---- O += P V ----
        for (int vc = 0; vc < 2; vc++) {
            #pragma unroll
            for (int i = 0; i < 8; i++) {
                int id = tid + i * 256;
                int bufl = id >> 10;
                int rid = id & 1023;
                int d = rid >> 3, c8 = rid & 7;
                const __nv_bfloat16* src = (bufl ? VTl : VTh)
                    + ((size_t)h * HD + d) * SQ + kb * 128 + vc * 64 + c8 * 8;
                *(uint4*)((bufl ? sVl : sVh) + d * (VSTR * 2) + c8 * 16) =
                    *(const uint4*)src;
            }
            __syncthreads();
            #pragma unroll
            for (int ks = 0; ks < 4; ks++) {
                uint32_t ah[2][4], al[2][4], bh[8][2], bl[8][2];
                const int kby = (vc * 64 + ks * 16 + tig * 2) * 2;
                #pragma unroll
                for (int mt = 0; mt < 2; mt++) {
                    const int r = wm * 32 + mt * 16 + g;
                    const char* p0 = sPh + r * (PSTR * 2) + kby;
                    const char* q0 = sPl + r * (PSTR * 2) + kby;
                    ah[mt][0] = *(const uint32_t*)p0;
                    ah[mt][1] = *(const uint32_t*)(p0 + 8 * (PSTR * 2));
                    ah[mt][2] = *(const uint32_t*)(p0 + 16);
                    ah[mt][3] = *(const uint32_t*)(p0 + 8 * (PSTR * 2) + 16);
                    al[mt][0] = *(const uint32_t*)q0;
                    al[mt][1] = *(const uint32_t*)(q0 + 8 * (PSTR * 2));
                    al[mt][2] = *(const uint32_t*)(q0 + 16);
                    al[mt][3] = *(const uint32_t*)(q0 + 8 * (PSTR * 2) + 16);
                }
                const int kby2 = (ks * 16 + tig * 2) * 2;
                #pragma unroll
                for (int j = 0; j < 8; j++) {
                    const int d = wn * 64 + j * 8 + g;
                    const char* p = sVh + d * (VSTR * 2) + kby2;
                    const char* q = sVl + d * (VSTR * 2) + kby2;
                    bh[j][0] = *(const uint32_t*)p;
                    bh[j][1] = *(const uint32_t*)(p + 16);
                    bl[j][0] = *(const uint32_t*)q;
                    bl[j][1] = *(const uint32_t*)(q + 16);
                }
                #pragma unroll
                for (int mt = 0; mt < 2; mt++)
                    #pragma unroll
                    for (int j = 0; j < 8; j++) {
                        mma_bf16(O[mt][j], ah[mt], bh[j]);
                        mma_bf16(O[mt][j], al[mt], bh[j]);
                        mma_bf16(O[mt][j], ah[mt], bl[j]);
                    }
            }
            __syncthreads();
        }
    }

    // ---- finalize ----
    #pragma unroll
    for (int mt = 0; mt < 2; mt++) {
        const int r0 = wm * 32 + mt * 16 + g, r1 = r0 + 8;
        const float i0 = 1.0f / rowL[r0], i1 = 1.0f / rowL[r1];
        const int q0 = qb * 128 + r0, q1 = qb * 128 + r1;
        #pragma unroll
        for (int j = 0; j < 8; j++) {
            const int col = wn * 64 + j * 8 + tig * 2;
            *(float2*)&Ctx[(size_t)q0 * (NH * HD) + h * HD + col] =
                make_float2(O[mt][j][0] * i0, O[mt][j][1] * i0);
            *(float2*)&Ctx[(size_t)q1 * (NH * HD) + h * HD + col] =
                make_float2(O[mt][j][2] * i1, O[mt][j][3] * i1);
        }
    }
}

// ---------------- launch ----------------------------------------------------
extern "C" void kernel_launch(void* const* d_in, const int* in_sizes, int n_in,
                              void* d_out, int out_size)
{
    const float* x   = (const float*)d_in[0];
    const float* kdw = (const float*)d_in[1];
    const float* kdb = (const float*)d_in[2];
    const float* kuw = (const float*)d_in[3];
    const float* kub = (const float*)d_in[4];
    const float* vuw = (const float*)d_in[5];
    const float* vub = (const float*)d_in[6];
    const float* krw = (const float*)d_in[7];
    const float* krb = (const float*)d_in[8];
    const float* qdw = (const float*)d_in[9];
    const float* qdb = (const float*)d_in[10];
    const float* quw = (const float*)d_in[11];
    const float* qub = (const float*)d_in[12];
    const float* qrw = (const float*)d_in[13];
    const float* qrb = (const float*)d_in[14];
    const float* ow  = (const float*)d_in[15];
    const float* ob  = (const float*)d_in[16];
    float* out = (float*)d_out;

    float *p_kvc, *p_qc, *p_ctx, *p_krw, *p_qrw, *p_krb, *p_qrb;
    __nv_bfloat16 *p_qh, *p_kh, *p_vth, *p_vtl;
    cudaGetSymbolAddress((void**)&p_kvc, g_kv_c);
    cudaGetSymbolAddress((void**)&p_qc,  g_q_c);
    cudaGetSymbolAddress((void**)&p_ctx, g_ctx);
    cudaGetSymbolAddress((void**)&p_krw, g_krw);
    cudaGetSymbolAddress((void**)&p_qrw, g_qrw);
    cudaGetSymbolAddress((void**)&p_krb, g_krb);
    cudaGetSymbolAddress((void**)&p_qrb, g_qrb);
    cudaGetSymbolAddress((void**)&p_qh,  g_qh);
    cudaGetSymbolAddress((void**)&p_kh,  g_kh);
    cudaGetSymbolAddress((void**)&p_vth, g_vth);
    cudaGetSymbolAddress((void**)&p_vtl, g_vtl);

    const float scale = 1.0f / sqrtf((float)DTOT);
    cudaFuncSetAttribute(gemm_tc, cudaFuncAttributeMaxDynamicSharedMemorySize, GT_SMEM);
    cudaFuncSetAttribute(attn3, cudaFuncAttributeMaxDynamicSharedMemorySize, ATTN_SMEM);
    dim3 blk(256);

    rotate_w<<<dim3((KVC + 255) / 256, NH * RD / 2), blk>>>(krw, krb, p_krw, p_krb, KVC);
    rotate_w<<<dim3((QC  + 255) / 256, NH * RD / 2), blk>>>(qrw, qrb, p_qrw, p_qrb, QC);

    // down projections (fp32 out)
    gemm_tc<<<dim3(KVC / 128, SQ / 128), blk, GT_SMEM>>>(
        x, kdw, kdb, p_kvc, nullptr, nullptr, HID, KVC, 0, KVC, 0, 1.0f, 0);
    gemm_tc<<<dim3(QC / 128, SQ / 128), blk, GT_SMEM>>>(
        x, qdw, qdb, p_qc, nullptr, nullptr, HID, QC, 0, QC, 0, 1.0f, 0);

    // up projections -> bf16 head-major / transposed layouts
    gemm_tc<<<dim3(2048 / 128, SQ / 128), blk, GT_SMEM>>>(
        p_kvc, kuw, kub, nullptr, p_kh, nullptr, KVC, HD, SQ * DTOT, DTOT, 0, 1.0f, 1);
    gemm_tc<<<dim3(1024 / 128, SQ / 128), blk, GT_SMEM>>>(
        p_kvc, p_krw, p_krb, nullptr, p_kh, nullptr, KVC, RD, SQ * DTOT, DTOT, HD, 1.0f, 1);
    gemm_tc<<<dim3(2048 / 128, SQ / 128), blk, GT_SMEM>>>(
        p_kvc, vuw, vub, nullptr, p_vth, p_vtl, KVC, HD, 0, 0, 0, 1.0f, 2);
    gemm_tc<<<dim3(2048 / 128, SQ / 128), blk, GT_SMEM>>>(
        p_qc, quw, qub, nullptr, p_qh, nullptr, QC, HD, SQ * DTOT, DTOT, 0, scale, 1);
    gemm_tc<<<dim3(1024 / 128, SQ / 128), blk, GT_SMEM>>>(
        p_qc, p_qrw, p_qrb, nullptr, p_qh, nullptr, QC, RD, SQ * DTOT, DTOT, HD, scale, 1);

    // attention
    attn3<<<dim3(SQ / 128, NH), blk, ATTN_SMEM>>>(p_qh, p_kh, p_vth, p_vtl, p_ctx);

    // output projection (fp32 out)
    gemm_tc<<<dim3(2048 / 128, SQ / 128), blk, GT_SMEM>>>(
        p_ctx, ow, ob, out, nullptr, nullptr, 2048, 2048, 0, 2048, 0, 1.0f, 0);
}

// round 6
// speedup vs baseline: 6.6917x; 1.3969x over previous
#include <cuda_runtime.h>
#include <cuda_bf16.h>
#include <math.h>
#include <stdint.h>

#define SQ   2048
#define HID  2048
#define NH   16
#define HD   128
#define RD   64
#define DTOT 192
#define KVC  512
#define QC   1024

typedef __nv_bfloat16 bf16;

// ---------------- scratch (bf16 hi/lo world) --------------------------------
__device__ bf16 g_xh[SQ * HID],      g_xl[SQ * HID];
__device__ bf16 g_kdwh[KVC * HID],   g_kdwl[KVC * HID];
__device__ bf16 g_qdwh[QC * HID],    g_qdwl[QC * HID];
__device__ bf16 g_kuwh[NH*HD*KVC],   g_kuwl[NH*HD*KVC];
__device__ bf16 g_vuwh[NH*HD*KVC],   g_vuwl[NH*HD*KVC];
__device__ bf16 g_quwh[NH*HD*QC],    g_quwl[NH*HD*QC];
__device__ bf16 g_owh[HID*NH*HD],    g_owl[HID*NH*HD];
__device__ bf16 g_krwh[NH*RD*KVC],   g_krwl[NH*RD*KVC];
__device__ bf16 g_qrwh[NH*RD*QC],    g_qrwl[NH*RD*QC];
__device__ float g_krb2[NH*RD], g_qrb2[NH*RD];
__device__ bf16 g_kvch[SQ*KVC],      g_kvcl[SQ*KVC];
__device__ bf16 g_qch[SQ*QC],        g_qcl[SQ*QC];
__device__ bf16 g_qh[NH*SQ*DTOT];
__device__ bf16 g_kh[NH*SQ*DTOT];
__device__ bf16 g_vth[NH*HD*SQ],     g_vtl[NH*HD*SQ];
__device__ bf16 g_ctxh[SQ*NH*HD],    g_ctxl[SQ*NH*HD];

// ---------------- small helpers ----------------------------------------------
union BF2 { __nv_bfloat162 v; uint32_t u; };

__device__ __forceinline__ uint32_t smem_u32(const void* p) {
    uint32_t a;
    asm("{ .reg .u64 t; cvta.to.shared.u64 t, %1; cvt.u32.u64 %0, t; }"
        : "=r"(a) : "l"(p));
    return a;
}
__device__ __forceinline__ void mma_bf16(float* c, const uint32_t* a, const uint32_t* b)
{
    asm volatile(
        "mma.sync.aligned.m16n8k16.row.col.f32.bf16.bf16.f32 "
        "{%0,%1,%2,%3}, {%4,%5,%6,%7}, {%8,%9}, {%0,%1,%2,%3};"
        : "+f"(c[0]), "+f"(c[1]), "+f"(c[2]), "+f"(c[3])
        : "r"(a[0]), "r"(a[1]), "r"(a[2]), "r"(a[3]), "r"(b[0]), "r"(b[1]));
}
__device__ __forceinline__ void ldsm4(uint32_t* r, uint32_t a) {
    asm volatile("ldmatrix.sync.aligned.m8n8.x4.shared.b16 {%0,%1,%2,%3}, [%4];"
        : "=r"(r[0]), "=r"(r[1]), "=r"(r[2]), "=r"(r[3]) : "r"(a));
}
__device__ __forceinline__ void cp16(uint32_t d, const void* s) {
    asm volatile("cp.async.cg.shared.global [%0], [%1], 16;" :: "r"(d), "l"(s));
}
#define CP_COMMIT() asm volatile("cp.async.commit_group;" ::: "memory")
#define CP_WAIT(n)  asm volatile("cp.async.wait_group %0;" :: "n"(n) : "memory")

// ---------------- split kernels ----------------------------------------------
__global__ void splitk(const float* __restrict__ X, bf16* __restrict__ Xh,
                       bf16* __restrict__ Xl, int n4)
{
    int i = blockIdx.x * 256 + threadIdx.x;
    if (i >= n4) return;
    float4 f = ((const float4*)X)[i];
    BF2 h0, h1, l0, l1;
    h0.v = __floats2bfloat162_rn(f.x, f.y);
    h1.v = __floats2bfloat162_rn(f.z, f.w);
    float2 g0 = __bfloat1622float2(h0.v), g1 = __bfloat1622float2(h1.v);
    l0.v = __floats2bfloat162_rn(f.x - g0.x, f.y - g0.y);
    l1.v = __floats2bfloat162_rn(f.z - g1.x, f.w - g1.y);
    ((uint2*)Xh)[i] = make_uint2(h0.u, h1.u);
    ((uint2*)Xl)[i] = make_uint2(l0.u, l1.u);
}

// rotate head-indexed "rope" into weights and split to hi/lo
__global__ void rotate_split(const float* __restrict__ W, const float* __restrict__ b,
                             bf16* __restrict__ Wh, bf16* __restrict__ Wl,
                             float* __restrict__ bo, int K)
{
    int pair = blockIdx.y;
    int h = pair >> 5;
    int i = pair & 31;
    float inv = powf(10000.0f, -(2.0f * (float)i) / 64.0f);
    float ang = (float)h * inv;
    float c = cosf(ang), s = sinf(ang);
    int c0 = pair * 2;
    int idx = blockIdx.x * 256 + threadIdx.x;
    if (idx < K) {
        float w1 = W[(size_t)c0 * K + idx];
        float w2 = W[(size_t)(c0 + 1) * K + idx];
        float r1 = c * w1 - s * w2;
        float r2 = s * w1 + c * w2;
        bf16 h1 = __float2bfloat16(r1);
        bf16 h2 = __float2bfloat16(r2);
        Wh[(size_t)c0 * K + idx]       = h1;
        Wh[(size_t)(c0 + 1) * K + idx] = h2;
        Wl[(size_t)c0 * K + idx]       = __float2bfloat16(r1 - __bfloat162float(h1));
        Wl[(size_t)(c0 + 1) * K + idx] = __float2bfloat16(r2 - __bfloat162float(h2));
    }
    if (idx == 0 && blockIdx.x == 0) {
        float b1 = b[c0], b2 = b[c0 + 1];
        bo[c0]     = c * b1 - s * b2;
        bo[c0 + 1] = s * b1 + c * b2;
    }
}

// ---------------- pure-bf16 tensor GEMM (cp.async + ldmatrix) ----------------
// C = scale*(Ah+Al)(Bh+Bl)^T + bias, 3-pass. A:[M,K], B:[N,K] bf16 hi/lo.
// MODE 0: fp32 out, head-scatter. MODE 1: bf16 out, head-scatter.
// MODE 2: bf16 hi/lo transposed [head][d][s]. MODE 3: bf16 hi/lo plain rows.
#define GMAT 18432                 // 128 rows * 144 B
#define GBUF (4 * GMAT)            // 73728
#define GT_SMEM (2 * GBUF)         // 147456

__device__ __forceinline__ void gemm_issue(
    uint32_t sb, int buf, int tid,
    const bf16* a0, const bf16* a1, const bf16* b0, const bf16* b1,
    int K, int c)
{
    const bf16* mats[4] = {a0, a1, b0, b1};
    #pragma unroll
    for (int i = 0; i < 16; i++) {
        const int mat = i >> 2;
        const int row = ((i & 3) << 5) + (tid >> 3);
        const int seg = tid & 7;
        const bf16* src = mats[mat] + (size_t)row * K + c * 64 + seg * 8;
        uint32_t dst = sb + buf * GBUF + mat * GMAT + row * 144 + seg * 16;
        cp16(dst, src);
    }
}

template<int MODE>
__global__ __launch_bounds__(256) void gemm_bf(
    const bf16* __restrict__ Ah, const bf16* __restrict__ Al,
    const bf16* __restrict__ Bh, const bf16* __restrict__ Bl,
    const float* __restrict__ bias,
    float* __restrict__ C, bf16* __restrict__ Cb, bf16* __restrict__ Cb2,
    int K, int head_sz, int head_stride, int row_stride, int col_off, float scale)
{
    extern __shared__ char smem[];
    const uint32_t sb = smem_u32(smem);
    const int tid = threadIdx.x, lane = tid & 31, wid = tid >> 5;
    const int tig = lane & 3, g = lane >> 2;
    const int wm = wid & 3, wn = wid >> 2;
    const int bm = blockIdx.y * 128, bn = blockIdx.x * 128;

    const bf16* a0 = Ah + (size_t)bm * K;
    const bf16* a1 = Al + (size_t)bm * K;
    const bf16* b0 = Bh + (size_t)bn * K;
    const bf16* b1 = Bl + (size_t)bn * K;

    float acc[2][8][4] = {};

    const uint32_t aoff = (uint32_t)((wm * 32 + (lane & 15)) * 144 + ((lane >> 4) << 4));
    const uint32_t boff = (uint32_t)((wn * 64 + (lane & 7) + ((lane >> 4) << 3)) * 144
                                     + (((lane >> 3) & 1) << 4));
    const int nch = K >> 6;

    gemm_issue(sb, 0, tid, a0, a1, b0, b1, K, 0);
    CP_COMMIT();

    for (int c = 0; c < nch; c++) {
        if (c + 1 < nch) {
            gemm_issue(sb, (c + 1) & 1, tid, a0, a1, b0, b1, K, c + 1);
            CP_COMMIT();
            CP_WAIT(1);
        } else {
            CP_WAIT(0);
        }
        __syncthreads();

        const uint32_t base = sb + (c & 1) * GBUF;
        const uint32_t aA = base + aoff;
        const uint32_t bB = base + 2 * GMAT + boff;
        #pragma unroll
        for (int ks = 0; ks < 4; ks++) {
            const uint32_t o = ks * 32;
            uint32_t ah[2][4], al[2][4], bh[4][4], bl[4][4];
            ldsm4(ah[0], aA + o);
            ldsm4(ah[1], aA + 2304 + o);
            ldsm4(al[0], aA + GMAT + o);
            ldsm4(al[1], aA + GMAT + 2304 + o);
            #pragma unroll
            for (int jp = 0; jp < 4; jp++) {
                ldsm4(bh[jp], bB + jp * 2304 + o);
                ldsm4(bl[jp], bB + GMAT + jp * 2304 + o);
            }
            #pragma unroll
            for (int mt = 0; mt < 2; mt++)
                #pragma unroll
                for (int jp = 0; jp < 4; jp++) {
                    mma_bf16(acc[mt][2*jp],   ah[mt], &bh[jp][0]);
                    mma_bf16(acc[mt][2*jp],   al[mt], &bh[jp][0]);
                    mma_bf16(acc[mt][2*jp],   ah[mt], &bl[jp][0]);
                    mma_bf16(acc[mt][2*jp+1], ah[mt], &bh[jp][2]);
                    mma_bf16(acc[mt][2*jp+1], al[mt], &bh[jp][2]);
                    mma_bf16(acc[mt][2*jp+1], ah[mt], &bl[jp][2]);
                }
        }
        __syncthreads();
    }

    if (MODE == 0 || MODE == 1) {
        #pragma unroll
        for (int mt = 0; mt < 2; mt++) {
            const int row_lo = bm + wm * 32 + mt * 16 + g;
            const int row_hi = row_lo + 8;
            #pragma unroll
            for (int j = 0; j < 8; j++) {
                const int col = bn + wn * 64 + j * 8 + tig * 2;
                float2 bv = *(const float2*)(bias + col);
                const int dst0 = (col / head_sz) * head_stride + col_off + (col % head_sz);
                float v0x = (acc[mt][j][0] + bv.x) * scale;
                float v0y = (acc[mt][j][1] + bv.y) * scale;
                float v1x = (acc[mt][j][2] + bv.x) * scale;
                float v1y = (acc[mt][j][3] + bv.y) * scale;
                if (MODE == 0) {
                    *(float2*)&C[(size_t)row_lo * row_stride + dst0] = make_float2(v0x, v0y);
                    *(float2*)&C[(size_t)row_hi * row_stride + dst0] = make_float2(v1x, v1y);
                } else {
                    BF2 t0, t1;
                    t0.v = __floats2bfloat162_rn(v0x, v0y);
                    t1.v = __floats2bfloat162_rn(v1x, v1y);
                    *(uint32_t*)&Cb[(size_t)row_lo * row_stride + dst0] = t0.u;
                    *(uint32_t*)&Cb[(size_t)row_hi * row_stride + dst0] = t1.u;
                }
            }
        }
    } else if (MODE == 3) {
        #pragma unroll
        for (int mt = 0; mt < 2; mt++) {
            const int row_lo = bm + wm * 32 + mt * 16 + g;
            const int row_hi = row_lo + 8;
            #pragma unroll
            for (int j = 0; j < 8; j++) {
                const int col = bn + wn * 64 + j * 8 + tig * 2;
                float2 bv = *(const float2*)(bias + col);
                float v0x = (acc[mt][j][0] + bv.x) * scale;
                float v0y = (acc[mt][j][1] + bv.y) * scale;
                float v1x = (acc[mt][j][2] + bv.x) * scale;
                float v1y = (acc[mt][j][3] + bv.y) * scale;
                BF2 h0, h1, l0, l1;
                h0.v = __floats2bfloat162_rn(v0x, v0y);
                h1.v = __floats2bfloat162_rn(v1x, v1y);
                float2 g0 = __bfloat1622float2(h0.v), g1 = __bfloat1622float2(h1.v);
                l0.v = __floats2bfloat162_rn(v0x - g0.x, v0y - g0.y);
                l1.v = __floats2bfloat162_rn(v1x - g1.x, v1y - g1.y);
                *(uint32_t*)&Cb [(size_t)row_lo * row_stride + col] = h0.u;
                *(uint32_t*)&Cb [(size_t)row_hi * row_stride + col] = h1.u;
                *(uint32_t*)&Cb2[(size_t)row_lo * row_stride + col] = l0.u;
                *(uint32_t*)&Cb2[(size_t)row_hi * row_stride + col] = l1.u;
            }
        }
    } else {
        // MODE 2: values — transpose to [head][d][s] bf16 hi/lo via smem staging
        float* ep = (float*)smem;
        #pragma unroll
        for (int mt = 0; mt < 2; mt++) {
            const int r0 = wm * 32 + mt * 16 + g;
            #pragma unroll
            for (int j = 0; j < 8; j++) {
                const int cl = wn * 64 + j * 8 + tig * 2;
                *(float2*)&ep[r0 * 132 + cl]       = make_float2(acc[mt][j][0], acc[mt][j][1]);
                *(float2*)&ep[(r0 + 8) * 132 + cl] = make_float2(acc[mt][j][2], acc[mt][j][3]);
            }
        }
        __syncthreads();
        const int d = tid >> 1, sh = tid & 1;
        const int head = bn >> 7;
        const float bv = bias[bn + d];
        #pragma unroll
        for (int s8 = 0; s8 < 8; s8++) {
            const int sl = sh * 64 + s8 * 8;
            union { bf16 b[8]; uint4 u; } hh, ll;
            #pragma unroll
            for (int u = 0; u < 8; u++) {
                float v = (ep[(sl + u) * 132 + d] + bv) * scale;
                hh.b[u] = __float2bfloat16(v);
                ll.b[u] = __float2bfloat16(v - __bfloat162float(hh.b[u]));
            }
            size_t base = ((size_t)head * HD + d) * SQ + bm + sl;
            *(uint4*)&Cb[base]  = hh.u;
            *(uint4*)&Cb2[base] = ll.u;
        }
    }
}

// ---------------- tensor-core flash attention (cp.async + ldmatrix) ----------
#define AS_Q    0
#define AS_K    51200
#define AS_PH   88064
#define AS_PL   122880
#define AS_VH   157696
#define AS_VL   192512
#define AS_REDM 227328
#define AS_REDL 228352
#define AS_ROWM 229376
#define AS_ROWC 229888
#define AS_ROWL 230400
#define ATTN_SMEM 230912

__device__ __forceinline__ float expapx(float x)
{
    if (x > -0.0625f)
        return 1.0f + x * (1.0f + x * (0.5f + x * 0.16666667f));
    return __expf(x);
}

__global__ __launch_bounds__(256) void attn4(
    const bf16* __restrict__ Qg, const bf16* __restrict__ Kg,
    const bf16* __restrict__ VTh, const bf16* __restrict__ VTl,
    bf16* __restrict__ Ctxh, bf16* __restrict__ Ctxl)
{
    extern __shared__ char sm[];
    const uint32_t sb = smem_u32(sm);
    float* redM = (float*)(sm + AS_REDM);
    float* redL = (float*)(sm + AS_REDL);
    float* rowM = (float*)(sm + AS_ROWM);
    float* rowC = (float*)(sm + AS_ROWC);
    float* rowL = (float*)(sm + AS_ROWL);

    const int qb = blockIdx.x, hh = blockIdx.y;
    const int tid = threadIdx.x;
    const int lane = tid & 31, wid = tid >> 5;
    const int g = lane >> 2, tig = lane & 3;
    const int wm = wid & 3, wn = wid >> 2;

    const bf16* Qh = Qg + ((size_t)hh * SQ + qb * 128) * DTOT;
    const bf16* Kh = Kg + (size_t)hh * SQ * DTOT;

    // Q -> smem once (stride 400 B)
    #pragma unroll
    for (int i = 0; i < 12; i++) {
        int id = tid + i * 256;
        int r = id / 24, c8 = id % 24;
        *(uint4*)(sm + AS_Q + r * 400 + c8 * 16) =
            *(const uint4*)(Qh + (size_t)r * DTOT + c8 * 8);
    }
    if (tid < 128) { rowM[tid] = -INFINITY; rowL[tid] = 0.0f; }

    float O[2][8][4] = {};

    // ldmatrix per-lane offsets
    const uint32_t aQ0 = sb + AS_Q + (wm * 32 + (lane & 15)) * 400 + ((lane >> 4) << 4);
    const uint32_t bK0 = (uint32_t)((wn * 64 + (lane & 7) + ((lane >> 4) << 3)) * 144
                                    + (((lane >> 3) & 1) << 4));
    const uint32_t aP0 = sb + AS_PH + (wm * 32 + (lane & 15)) * 272 + ((lane >> 4) << 4);
    const uint32_t bV0 = sb + AS_VH + (wn * 64 + (lane & 7) + ((lane >> 4) << 3)) * 272
                         + (((lane >> 3) & 1) << 4);

    for (int kb = 0; kb < SQ / 128; kb++) {
        // issue K chunk 0, then V (so K0 completes first)
        #pragma unroll
        for (int i = 0; i < 4; i++) {
            int id = tid + i * 256;
            int r = id >> 3, seg = id & 7;
            cp16(sb + AS_K + r * 144 + seg * 16,
                 Kh + (size_t)(kb * 128 + r) * DTOT + seg * 8);
        }
        CP_COMMIT();
        #pragma unroll
        for (int i = 0; i < 16; i++) {
            int id = tid + i * 256;
            int mat = id >> 11, rid = id & 2047;
            int r = rid >> 4, seg = rid & 15;
            const bf16* src = (mat ? VTl : VTh)
                + ((size_t)hh * HD + r) * SQ + kb * 128 + seg * 8;
            cp16(sb + (mat ? AS_VL : AS_VH) + r * 272 + seg * 16, src);
        }
        CP_COMMIT();

        float S[2][8][4] = {};
        #pragma unroll
        for (int kc = 0; kc < 3; kc++) {
            if (kc < 2) {
                #pragma unroll
                for (int i = 0; i < 4; i++) {
                    int id = tid + i * 256;
                    int r = id >> 3, seg = id & 7;
                    cp16(sb + AS_K + ((kc + 1) & 1) * 18432 + r * 144 + seg * 16,
                         Kh + (size_t)(kb * 128 + r) * DTOT + (kc + 1) * 64 + seg * 8);
                }
                CP_COMMIT();
            }
            if (kc == 0) CP_WAIT(2);
            else if (kc == 1) CP_WAIT(1);
            else CP_WAIT(0);
            __syncthreads();

            const uint32_t bK = sb + AS_K + (kc & 1) * 18432 + bK0;
            #pragma unroll
            for (int ks = 0; ks < 4; ks++) {
                const uint32_t o = ks * 32;
                uint32_t a[2][4], b[4][4];
                ldsm4(a[0], aQ0 + kc * 128 + o);
                ldsm4(a[1], aQ0 + kc * 128 + 6400 + o);   // +16 rows * 400
                #pragma unroll
                for (int jp = 0; jp < 4; jp++)
                    ldsm4(b[jp], bK + jp * 2304 + o);
                #pragma unroll
                for (int mt = 0; mt < 2; mt++)
                    #pragma unroll
                    for (int jp = 0; jp < 4; jp++) {
                        mma_bf16(S[mt][2*jp],   a[mt], &b[jp][0]);
                        mma_bf16(S[mt][2*jp+1], a[mt], &b[jp][2]);
                    }
            }
            __syncthreads();
        }

        // ---- softmax ----
        #pragma unroll
        for (int mt = 0; mt < 2; mt++) {
            float m0 = -INFINITY, m1 = -INFINITY;
            #pragma unroll
            for (int j = 0; j < 8; j++) {
                m0 = fmaxf(m0, fmaxf(S[mt][j][0], S[mt][j][1]));
                m1 = fmaxf(m1, fmaxf(S[mt][j][2], S[mt][j][3]));
            }
            m0 = fmaxf(m0, __shfl_xor_sync(~0u, m0, 1));
            m0 = fmaxf(m0, __shfl_xor_sync(~0u, m0, 2));
            m1 = fmaxf(m1, __shfl_xor_sync(~0u, m1, 1));
            m1 = fmaxf(m1, __shfl_xor_sync(~0u, m1, 2));
            if (tig == 0) {
                redM[(wm * 32 + mt * 16 + g) * 2 + wn] = m0;
                redM[(wm * 32 + mt * 16 + g + 8) * 2 + wn] = m1;
            }
        }
        __syncthreads();
        if (wn == 0 && tig == 0) {
            #pragma unroll
            for (int mt = 0; mt < 2; mt++)
                #pragma unroll
                for (int hf = 0; hf < 2; hf++) {
                    int r = wm * 32 + mt * 16 + hf * 8 + g;
                    float tm = fmaxf(redM[r * 2], redM[r * 2 + 1]);
                    float mo = rowM[r];
                    float mn = fmaxf(mo, tm);
                    rowM[r] = mn;
                    rowC[r] = __expf(mo - mn);
                }
        }
        __syncthreads();

        #pragma unroll
        for (int mt = 0; mt < 2; mt++) {
            const int r0 = wm * 32 + mt * 16 + g, r1 = r0 + 8;
            const float mn0 = rowM[r0], mn1 = rowM[r1];
            const float c0 = rowC[r0], c1 = rowC[r1];
            float s0 = 0.0f, s1 = 0.0f;
            #pragma unroll
            for (int j = 0; j < 8; j++) {
                const int col = wn * 64 + j * 8 + tig * 2;
                float p00 = expapx(S[mt][j][0] - mn0);
                float p01 = expapx(S[mt][j][1] - mn0);
                float p10 = expapx(S[mt][j][2] - mn1);
                float p11 = expapx(S[mt][j][3] - mn1);
                s0 += p00 + p01;
                s1 += p10 + p11;
                BF2 h0, l0, h1, l1;
                h0.v = __floats2bfloat162_rn(p00, p01);
                float2 hf0 = __bfloat1622float2(h0.v);
                l0.v = __floats2bfloat162_rn(p00 - hf0.x, p01 - hf0.y);
                h1.v = __floats2bfloat162_rn(p10, p11);
                float2 hf1 = __bfloat1622float2(h1.v);
                l1.v = __floats2bfloat162_rn(p10 - hf1.x, p11 - hf1.y);
                *(uint32_t*)(sm + AS_PH + r0 * 272 + col * 2) = h0.u;
                *(uint32_t*)(sm + AS_PL + r0 * 272 + col * 2) = l0.u;
                *(uint32_t*)(sm + AS_PH + r1 * 272 + col * 2) = h1.u;
                *(uint32_t*)(sm + AS_PL + r1 * 272 + col * 2) = l1.u;
                O[mt][j][0] *= c0; O[mt][j][1] *= c0;
                O[mt][j][2] *= c1; O[mt][j][3] *= c1;
            }
            s0 += __shfl_xor_sync(~0u, s0, 1);
            s0 += __shfl_xor_sync(~0u, s0, 2);
            s1 += __shfl_xor_sync(~0u, s1, 1);
            s1 += __shfl_xor_sync(~0u, s1, 2);
            if (tig == 0) { redL[r0 * 2 + wn] = s0; redL[r1 * 2 + wn] = s1; }
        }
        __syncthreads();
        if (wn == 0 && tig == 0) {
            #pragma unroll
            for (int mt = 0; mt < 2; mt++)
                #pragma unroll
                for (int hf = 0; hf < 2; hf++) {
                    int r = wm * 32 + mt * 16 + hf * 8 + g;
                    rowL[r] = rowL[r] * rowC[r] + redL[r * 2] + redL[r * 2 + 1];
                }
        }

        // ---- O += P V  (V already resident; 8 k-steps of 16) ----
        #pragma unroll
        for (int ks = 0; ks < 8; ks++) {
            const uint32_t o = ks * 32;
            uint32_t ah[2][4], al[2][4], bh[4][4], bl[4][4];
            ldsm4(ah[0], aP0 + o);
            ldsm4(ah[1], aP0 + 4352 + o);          // +16 rows * 272
            ldsm4(al[0], aP0 + 34816 + o);
            ldsm4(al[1], aP0 + 34816 + 4352 + o);
            #pragma unroll
            for (int jp = 0; jp < 4; jp++) {
                ldsm4(bh[jp], bV0 + jp * 4352 + o);
                ldsm4(bl[jp], bV0 + 34816 + jp * 4352 + o);
            }
            #pragma unroll
            for (int mt = 0; mt < 2; mt++)
                #pragma unroll
                for (int jp = 0; jp < 4; jp++) {
                    mma_bf16(O[mt][2*jp],   ah[mt], &bh[jp][0]);
                    mma_bf16(O[mt][2*jp],   al[mt], &bh[jp][0]);
                    mma_bf16(O[mt][2*jp],   ah[mt], &bl[jp][0]);
                    mma_bf16(O[mt][2*jp+1], ah[mt], &bh[jp][2]);
                    mma_bf16(O[mt][2*jp+1], al[mt], &bh[jp][2]);
                    mma_bf16(O[mt][2*jp+1], ah[mt], &bl[jp][2]);
                }
        }
        __syncthreads();
    }

    // ---- finalize: ctx -> bf16 hi/lo ----
    #pragma unroll
    for (int mt = 0; mt < 2; mt++) {
        const int r0 = wm * 32 + mt * 16 + g, r1 = r0 + 8;
        const float i0 = 1.0f / rowL[r0], i1 = 1.0f / rowL[r1];
        const int q0 = qb * 128 + r0, q1 = qb * 128 + r1;
        #pragma unroll
        for (int j = 0; j < 8; j++) {
            const int col = hh * HD + wn * 64 + j * 8 + tig * 2;
            float v0x = O[mt][j][0] * i0, v0y = O[mt][j][1] * i0;
            float v1x = O[mt][j][2] * i1, v1y = O[mt][j][3] * i1;
            BF2 h0, l0, h1, l1;
            h0.v = __floats2bfloat162_rn(v0x, v0y);
            float2 f0 = __bfloat1622float2(h0.v);
            l0.v = __floats2bfloat162_rn(v0x - f0.x, v0y - f0.y);
            h1.v = __floats2bfloat162_rn(v1x, v1y);
            float2 f1 = __bfloat1622float2(h1.v);
            l1.v = __floats2bfloat162_rn(v1x - f1.x, v1y - f1.y);
            *(uint32_t*)&Ctxh[(size_t)q0 * (NH * HD) + col] = h0.u;
            *(uint32_t*)&Ctxl[(size_t)q0 * (NH * HD) + col] = l0.u;
            *(uint32_t*)&Ctxh[(size_t)q1 * (NH * HD) + col] = h1.u;
            *(uint32_t*)&Ctxl[(size_t)q1 * (NH * HD) + col] = l1.u;
        }
    }
}

// ---------------- launch ----------------------------------------------------
extern "C" void kernel_launch(void* const* d_in, const int* in_sizes, int n_in,
                              void* d_out, int out_size)
{
    const float* x   = (const float*)d_in[0];
    const float* kdw = (const float*)d_in[1];
    const float* kdb = (const float*)d_in[2];
    const float* kuw = (const float*)d_in[3];
    const float* kub = (const float*)d_in[4];
    const float* vuw = (const float*)d_in[5];
    const float* vub = (const float*)d_in[6];
    const float* krw = (const float*)d_in[7];
    const float* krb = (const float*)d_in[8];
    const float* qdw = (const float*)d_in[9];
    const float* qdb = (const float*)d_in[10];
    const float* quw = (const float*)d_in[11];
    const float* qub = (const float*)d_in[12];
    const float* qrw = (const float*)d_in[13];
    const float* qrb = (const float*)d_in[14];
    const float* ow  = (const float*)d_in[15];
    const float* ob  = (const float*)d_in[16];
    float* out = (float*)d_out;

#define SYM(p, s) cudaGetSymbolAddress((void**)&p, s)
    bf16 *xh, *xl, *kdwh, *kdwl, *qdwh, *qdwl, *kuwh, *kuwl, *vuwh, *vuwl;
    bf16 *quwh, *quwl, *owh, *owl, *krwh, *krwl, *qrwh, *qrwl;
    bf16 *kvch, *kvcl, *qch, *qcl, *qhp, *khp, *vth, *vtl, *ctxh, *ctxl;
    float *krb2, *qrb2;
    SYM(xh, g_xh); SYM(xl, g_xl);
    SYM(kdwh, g_kdwh); SYM(kdwl, g_kdwl);
    SYM(qdwh, g_qdwh); SYM(qdwl, g_qdwl);
    SYM(kuwh, g_kuwh); SYM(kuwl, g_kuwl);
    SYM(vuwh, g_vuwh); SYM(vuwl, g_vuwl);
    SYM(quwh, g_quwh); SYM(quwl, g_quwl);
    SYM(owh, g_owh); SYM(owl, g_owl);
    SYM(krwh, g_krwh); SYM(krwl, g_krwl);
    SYM(qrwh, g_qrwh); SYM(qrwl, g_qrwl);
    SYM(kvch, g_kvch); SYM(kvcl, g_kvcl);
    SYM(qch, g_qch); SYM(qcl, g_qcl);
    SYM(qhp, g_qh); SYM(khp, g_kh);
    SYM(vth, g_vth); SYM(vtl, g_vtl);
    SYM(ctxh, g_ctxh); SYM(ctxl, g_ctxl);
    SYM(krb2, g_krb2); SYM(qrb2, g_qrb2);
#undef SYM

    const float scale = 1.0f / sqrtf((float)DTOT);
    cudaFuncSetAttribute(gemm_bf<0>, cudaFuncAttributeMaxDynamicSharedMemorySize, GT_SMEM);
    cudaFuncSetAttribute(gemm_bf<1>, cudaFuncAttributeMaxDynamicSharedMemorySize, GT_SMEM);
    cudaFuncSetAttribute(gemm_bf<2>, cudaFuncAttributeMaxDynamicSharedMemorySize, GT_SMEM);
    cudaFuncSetAttribute(gemm_bf<3>, cudaFuncAttributeMaxDynamicSharedMemorySize, GT_SMEM);
    cudaFuncSetAttribute(attn4, cudaFuncAttributeMaxDynamicSharedMemorySize, ATTN_SMEM);
    dim3 blk(256);

    // splits (one-time per call; inputs are fp32)
    splitk<<<SQ * HID / 1024, blk>>>(x, xh, xl, SQ * HID / 4);
    splitk<<<KVC * HID / 1024, blk>>>(kdw, kdwh, kdwl, KVC * HID / 4);
    splitk<<<QC * HID / 1024, blk>>>(qdw, qdwh, qdwl, QC * HID / 4);
    splitk<<<NH*HD*KVC / 1024, blk>>>(kuw, kuwh, kuwl, NH*HD*KVC / 4);
    splitk<<<NH*HD*KVC / 1024, blk>>>(vuw, vuwh, vuwl, NH*HD*KVC / 4);
    splitk<<<NH*HD*QC / 1024, blk>>>(quw, quwh, quwl, NH*HD*QC / 4);
    splitk<<<HID*NH*HD / 1024, blk>>>(ow, owh, owl, HID*NH*HD / 4);
    rotate_split<<<dim3((KVC + 255) / 256, NH * RD / 2), blk>>>(krw, krb, krwh, krwl, krb2, KVC);
    rotate_split<<<dim3((QC + 255) / 256, NH * RD / 2), blk>>>(qrw, qrb, qrwh, qrwl, qrb2, QC);

    // down projections -> bf16 hi/lo activations
    gemm_bf<3><<<dim3(KVC / 128, 16), blk, GT_SMEM>>>(
        xh, xl, kdwh, kdwl, kdb, nullptr, kvch, kvcl, HID, KVC, 0, KVC, 0, 1.0f);
    gemm_bf<3><<<dim3(QC / 128, 16), blk, GT_SMEM>>>(
        xh, xl, qdwh, qdwl, qdb, nullptr, qch, qcl, HID, QC, 0, QC, 0, 1.0f);

    // up projections
    gemm_bf<1><<<dim3(2048 / 128, 16), blk, GT_SMEM>>>(
        kvch, kvcl, kuwh, kuwl, kub, nullptr, khp, nullptr, KVC, HD, SQ*DTOT, DTOT, 0, 1.0f);
    gemm_bf<1><<<dim3(1024 / 128, 16), blk, GT_SMEM>>>(
        kvch, kvcl, krwh, krwl, krb2, nullptr, khp, nullptr, KVC, RD, SQ*DTOT, DTOT, HD, 1.0f);
    gemm_bf<2><<<dim3(2048 / 128, 16), blk, GT_SMEM>>>(
        kvch, kvcl, vuwh, vuwl, vub, nullptr, vth, vtl, KVC, HD, 0, 0, 0, 1.0f);
    gemm_bf<1><<<dim3(2048 / 128, 16), blk, GT_SMEM>>>(
        qch, qcl, quwh, quwl, qub, nullptr, qhp, nullptr, QC, HD, SQ*DTOT, DTOT, 0, scale);
    gemm_bf<1><<<dim3(1024 / 128, 16), blk, GT_SMEM>>>(
        qch, qcl, qrwh, qrwl, qrb2, nullptr, qhp, nullptr, QC, RD, SQ*DTOT, DTOT, HD, scale);

    // attention -> ctx hi/lo
    attn4<<<dim3(SQ / 128, NH), blk, ATTN_SMEM>>>(qhp, khp, vth, vtl, ctxh, ctxl);

    // output projection (fp32 out)
    gemm_bf<0><<<dim3(2048 / 128, 16), blk, GT_SMEM>>>(
        ctxh, ctxl, owh, owl, ob, out, nullptr, nullptr, 2048, 2048, 0, 2048, 0, 1.0f);
}

// round 7
// speedup vs baseline: 7.7682x; 1.1609x over previous
#include <cuda_runtime.h>
#include <cuda_bf16.h>
#include <math.h>
#include <stdint.h>

#define SQ   2048
#define HID  2048
#define NH   16
#define HD   128
#define RD   64
#define DTOT 192
#define KVC  512
#define QC   1024

typedef __nv_bfloat16 bf16;

// ---------------- scratch ----------------------------------------------------
__device__ bf16 g_xh[SQ * HID],      g_xl[SQ * HID];
__device__ bf16 g_kdwh[KVC * HID],   g_kdwl[KVC * HID];
__device__ bf16 g_qdwh[QC * HID];
__device__ bf16 g_kuwh[NH*HD*KVC];
__device__ bf16 g_vuwh[NH*HD*KVC],   g_vuwl[NH*HD*KVC];
__device__ bf16 g_quwh[NH*HD*QC];
__device__ bf16 g_owh[HID*NH*HD],    g_owl[HID*NH*HD];
__device__ bf16 g_krwh[NH*RD*KVC];
__device__ bf16 g_qrwh[NH*RD*QC];
__device__ float g_krb2[NH*RD], g_qrb2[NH*RD];
__device__ bf16 g_kvch[SQ*KVC],      g_kvcl[SQ*KVC];
__device__ bf16 g_qch[SQ*QC];
__device__ bf16 g_qh[NH*SQ*DTOT];
__device__ bf16 g_kh[NH*SQ*DTOT];
__device__ bf16 g_vth[NH*HD*SQ],     g_vtl[NH*HD*SQ];
__device__ bf16 g_ctxh[SQ*NH*HD],    g_ctxl[SQ*NH*HD];

// ---------------- helpers ----------------------------------------------------
union BF2 { __nv_bfloat162 v; uint32_t u; };

__device__ __forceinline__ uint32_t smem_u32(const void* p) {
    uint32_t a;
    asm("{ .reg .u64 t; cvta.to.shared.u64 t, %1; cvt.u32.u64 %0, t; }"
        : "=r"(a) : "l"(p));
    return a;
}
__device__ __forceinline__ void mma_bf16(float* c, const uint32_t* a, const uint32_t* b)
{
    asm volatile(
        "mma.sync.aligned.m16n8k16.row.col.f32.bf16.bf16.f32 "
        "{%0,%1,%2,%3}, {%4,%5,%6,%7}, {%8,%9}, {%0,%1,%2,%3};"
        : "+f"(c[0]), "+f"(c[1]), "+f"(c[2]), "+f"(c[3])
        : "r"(a[0]), "r"(a[1]), "r"(a[2]), "r"(a[3]), "r"(b[0]), "r"(b[1]));
}
__device__ __forceinline__ void ldsm4(uint32_t* r, uint32_t a) {
    asm volatile("ldmatrix.sync.aligned.m8n8.x4.shared.b16 {%0,%1,%2,%3}, [%4];"
        : "=r"(r[0]), "=r"(r[1]), "=r"(r[2]), "=r"(r[3]) : "r"(a));
}
__device__ __forceinline__ void cp16(uint32_t d, const void* s) {
    asm volatile("cp.async.cg.shared.global [%0], [%1], 16;" :: "r"(d), "l"(s));
}
#define CP_COMMIT() asm volatile("cp.async.commit_group;" ::: "memory")
#define CP_WAIT(n)  asm volatile("cp.async.wait_group %0;" :: "n"(n) : "memory")

// ---------------- fused splits ------------------------------------------------
struct SJob { const float* X; bf16* H; bf16* L; int b0; };
struct STab { SJob j[7]; };

__global__ void split_seg(STab t)
{
    int ji = 0;
    #pragma unroll
    for (int i = 1; i < 7; i++)
        if ((int)blockIdx.x >= t.j[i].b0) ji = i;
    const float* X = t.j[ji].X;
    bf16* H = t.j[ji].H;
    bf16* L = t.j[ji].L;
    int i = ((int)blockIdx.x - t.j[ji].b0) * 256 + threadIdx.x;
    float4 f = ((const float4*)X)[i];
    BF2 h0, h1;
    h0.v = __floats2bfloat162_rn(f.x, f.y);
    h1.v = __floats2bfloat162_rn(f.z, f.w);
    ((uint2*)H)[i] = make_uint2(h0.u, h1.u);
    if (L) {
        float2 g0 = __bfloat1622float2(h0.v), g1 = __bfloat1622float2(h1.v);
        BF2 l0, l1;
        l0.v = __floats2bfloat162_rn(f.x - g0.x, f.y - g0.y);
        l1.v = __floats2bfloat162_rn(f.z - g1.x, f.w - g1.y);
        ((uint2*)L)[i] = make_uint2(l0.u, l1.u);
    }
}

__global__ void rotate_split(const float* __restrict__ W, const float* __restrict__ b,
                             bf16* __restrict__ Wh, float* __restrict__ bo, int K)
{
    int pair = blockIdx.y;
    int h = pair >> 5;
    int i = pair & 31;
    float inv = powf(10000.0f, -(2.0f * (float)i) / 64.0f);
    float ang = (float)h * inv;
    float c = cosf(ang), s = sinf(ang);
    int c0 = pair * 2;
    int idx = blockIdx.x * 256 + threadIdx.x;
    if (idx < K) {
        float w1 = W[(size_t)c0 * K + idx];
        float w2 = W[(size_t)(c0 + 1) * K + idx];
        Wh[(size_t)c0 * K + idx]       = __float2bfloat16(c * w1 - s * w2);
        Wh[(size_t)(c0 + 1) * K + idx] = __float2bfloat16(s * w1 + c * w2);
    }
    if (idx == 0 && blockIdx.x == 0) {
        float b1 = b[c0], b2 = b[c0 + 1];
        bo[c0]     = c * b1 - s * b2;
        bo[c0 + 1] = s * b1 + c * b2;
    }
}

// ---------------- segmented tensor GEMM --------------------------------------
// K-chunk 32, stride 80 B, 2-stage cp.async, 2 CTAs/SM.
// modes: 0 fp32 scatter; 1 bf16 scatter; 2 V transpose hi/lo; 3 bf16 rows hi(+lo).
#define GST   80
#define GMATB (128 * GST)     // 10240
#define GSTG  (4 * GMATB)     // 40960
#define GT_SMEM (2 * GSTG)    // 81920

struct GSeg {
    const bf16 *Ah, *Al, *Bh, *Bl;
    const float* bias;
    float* C; bf16 *Cb; bf16 *Cb2;
    int K, head_sz, head_stride, row_stride, col_off;
    float scale;
    int mode, npass, bn0;
};
struct GTab { GSeg s[5]; int nseg; };

__global__ __launch_bounds__(256, 2) void gemm_seg(GTab tab)
{
    extern __shared__ char smem[];
    const uint32_t sb = smem_u32(smem);
    int si = 0;
    #pragma unroll
    for (int i = 1; i < 5; i++)
        if (i < tab.nseg && (int)blockIdx.x >= tab.s[i].bn0) si = i;
    const bf16* Ah = tab.s[si].Ah;
    const bf16* Al = tab.s[si].Al;
    const bf16* Bh = tab.s[si].Bh;
    const bf16* Bl = tab.s[si].Bl;
    const float* bias = tab.s[si].bias;
    const int K = tab.s[si].K;
    const int mode = tab.s[si].mode;
    const bool np3 = (tab.s[si].npass == 3);
    const int bn = ((int)blockIdx.x - tab.s[si].bn0) * 128;
    const int bm = blockIdx.y * 128;

    const int tid = threadIdx.x, lane = tid & 31, wid = tid >> 5;
    const int g = lane >> 2, tig = lane & 3;
    const int wm = wid & 3, wn = wid >> 2;

    const bf16* a0 = Ah + (size_t)bm * K;
    const bf16* a1 = np3 ? Al + (size_t)bm * K : a0;
    const bf16* b0 = Bh + (size_t)bn * K;
    const bf16* b1 = np3 ? Bl + (size_t)bn * K : b0;

    float acc[2][8][4] = {};

#define G_ISSUE(c, st) do { \
    uint32_t _base = sb + (st) * GSTG; \
    if (np3) { \
        _Pragma("unroll") \
        for (int _i = 0; _i < 8; _i++) { \
            int _id = tid + (_i << 8); \
            int _mat = _id >> 9, _rid = _id & 511; \
            int _row = _rid >> 2, _seg = _rid & 3; \
            const bf16* _mp = (_mat == 0) ? a0 : (_mat == 1) ? a1 : (_mat == 2) ? b0 : b1; \
            cp16(_base + _mat * GMATB + _row * GST + _seg * 16, \
                 _mp + (size_t)_row * K + (c) * 32 + _seg * 8); \
        } \
    } else { \
        _Pragma("unroll") \
        for (int _i = 0; _i < 4; _i++) { \
            int _id = tid + (_i << 8); \
            int _mat = (_id >> 9) ? 2 : 0, _rid = _id & 511; \
            int _row = _rid >> 2, _seg = _rid & 3; \
            const bf16* _mp = (_mat == 0) ? a0 : b0; \
            cp16(_base + _mat * GMATB + _row * GST + _seg * 16, \
                 _mp + (size_t)_row * K + (c) * 32 + _seg * 8); \
        } \
    } \
} while (0)

    const uint32_t aoff = (uint32_t)((wm * 32 + (lane & 15)) * GST + ((lane >> 4) << 4));
    const uint32_t boff = (uint32_t)(2 * GMATB
        + (wn * 64 + (lane & 7) + ((lane >> 4) << 3)) * GST + (((lane >> 3) & 1) << 4));

    const int nch = K >> 5;
    G_ISSUE(0, 0);
    CP_COMMIT();
    for (int c = 0; c < nch; c++) {
        if (c + 1 < nch) { G_ISSUE(c + 1, (c + 1) & 1); CP_COMMIT(); CP_WAIT(1); }
        else CP_WAIT(0);
        __syncthreads();
        const uint32_t aA = sb + (c & 1) * GSTG + aoff;
        const uint32_t bB = sb + (c & 1) * GSTG + boff;
        #pragma unroll
        for (int ks = 0; ks < 2; ks++) {
            const uint32_t o = ks * 32;
            uint32_t ah[2][4], bh[4][4];
            ldsm4(ah[0], aA + o);
            ldsm4(ah[1], aA + 1280 + o);
            #pragma unroll
            for (int jp = 0; jp < 4; jp++) ldsm4(bh[jp], bB + jp * 1280 + o);
            if (np3) {
                uint32_t al[2][4], bl[4][4];
                ldsm4(al[0], aA + GMATB + o);
                ldsm4(al[1], aA + GMATB + 1280 + o);
                #pragma unroll
                for (int jp = 0; jp < 4; jp++) ldsm4(bl[jp], bB + GMATB + jp * 1280 + o);
                #pragma unroll
                for (int mt = 0; mt < 2; mt++)
                    #pragma unroll
                    for (int jp = 0; jp < 4; jp++) {
                        mma_bf16(acc[mt][2*jp],   ah[mt], &bh[jp][0]);
                        mma_bf16(acc[mt][2*jp],   al[mt], &bh[jp][0]);
                        mma_bf16(acc[mt][2*jp],   ah[mt], &bl[jp][0]);
                        mma_bf16(acc[mt][2*jp+1], ah[mt], &bh[jp][2]);
                        mma_bf16(acc[mt][2*jp+1], al[mt], &bh[jp][2]);
                        mma_bf16(acc[mt][2*jp+1], ah[mt], &bl[jp][2]);
                    }
            } else {
                #pragma unroll
                for (int mt = 0; mt < 2; mt++)
                    #pragma unroll
                    for (int jp = 0; jp < 4; jp++) {
                        mma_bf16(acc[mt][2*jp],   ah[mt], &bh[jp][0]);
                        mma_bf16(acc[mt][2*jp+1], ah[mt], &bh[jp][2]);
                    }
            }
        }
        __syncthreads();
    }
#undef G_ISSUE

    const float scale = tab.s[si].scale;
    if (mode == 0 || mode == 1) {
        const int head_sz = tab.s[si].head_sz;
        const int head_stride = tab.s[si].head_stride;
        const int row_stride = tab.s[si].row_stride;
        const int col_off = tab.s[si].col_off;
        float* C = tab.s[si].C;
        bf16* Cb = tab.s[si].Cb;
        #pragma unroll
        for (int mt = 0; mt < 2; mt++) {
            const int row_lo = bm + wm * 32 + mt * 16 + g;
            const int row_hi = row_lo + 8;
            #pragma unroll
            for (int j = 0; j < 8; j++) {
                const int col = bn + wn * 64 + j * 8 + tig * 2;
                float2 bv = *(const float2*)(bias + col);
                const int dst0 = (col / head_sz) * head_stride + col_off + (col % head_sz);
                float v0x = (acc[mt][j][0] + bv.x) * scale;
                float v0y = (acc[mt][j][1] + bv.y) * scale;
                float v1x = (acc[mt][j][2] + bv.x) * scale;
                float v1y = (acc[mt][j][3] + bv.y) * scale;
                if (mode == 0) {
                    *(float2*)&C[(size_t)row_lo * row_stride + dst0] = make_float2(v0x, v0y);
                    *(float2*)&C[(size_t)row_hi * row_stride + dst0] = make_float2(v1x, v1y);
                } else {
                    BF2 t0, t1;
                    t0.v = __floats2bfloat162_rn(v0x, v0y);
                    t1.v = __floats2bfloat162_rn(v1x, v1y);
                    *(uint32_t*)&Cb[(size_t)row_lo * row_stride + dst0] = t0.u;
                    *(uint32_t*)&Cb[(size_t)row_hi * row_stride + dst0] = t1.u;
                }
            }
        }
    } else if (mode == 3) {
        const int row_stride = tab.s[si].row_stride;
        bf16* Cb = tab.s[si].Cb;
        bf16* Cb2 = tab.s[si].Cb2;
        #pragma unroll
        for (int mt = 0; mt < 2; mt++) {
            const int row_lo = bm + wm * 32 + mt * 16 + g;
            const int row_hi = row_lo + 8;
            #pragma unroll
            for (int j = 0; j < 8; j++) {
                const int col = bn + wn * 64 + j * 8 + tig * 2;
                float2 bv = *(const float2*)(bias + col);
                float v0x = (acc[mt][j][0] + bv.x) * scale;
                float v0y = (acc[mt][j][1] + bv.y) * scale;
                float v1x = (acc[mt][j][2] + bv.x) * scale;
                float v1y = (acc[mt][j][3] + bv.y) * scale;
                BF2 h0, h1;
                h0.v = __floats2bfloat162_rn(v0x, v0y);
                h1.v = __floats2bfloat162_rn(v1x, v1y);
                *(uint32_t*)&Cb[(size_t)row_lo * row_stride + col] = h0.u;
                *(uint32_t*)&Cb[(size_t)row_hi * row_stride + col] = h1.u;
                if (Cb2) {
                    float2 g0 = __bfloat1622float2(h0.v), g1 = __bfloat1622float2(h1.v);
                    BF2 l0, l1;
                    l0.v = __floats2bfloat162_rn(v0x - g0.x, v0y - g0.y);
                    l1.v = __floats2bfloat162_rn(v1x - g1.x, v1y - g1.y);
                    *(uint32_t*)&Cb2[(size_t)row_lo * row_stride + col] = l0.u;
                    *(uint32_t*)&Cb2[(size_t)row_hi * row_stride + col] = l1.u;
                }
            }
        }
    } else {
        // mode 2: values — transpose to [head][d][s] bf16 hi/lo via smem staging
        bf16* Cb = tab.s[si].Cb;
        bf16* Cb2 = tab.s[si].Cb2;
        float* ep = (float*)smem;
        #pragma unroll
        for (int mt = 0; mt < 2; mt++) {
            const int r0 = wm * 32 + mt * 16 + g;
            #pragma unroll
            for (int j = 0; j < 8; j++) {
                const int cl = wn * 64 + j * 8 + tig * 2;
                *(float2*)&ep[r0 * 132 + cl]       = make_float2(acc[mt][j][0], acc[mt][j][1]);
                *(float2*)&ep[(r0 + 8) * 132 + cl] = make_float2(acc[mt][j][2], acc[mt][j][3]);
            }
        }
        __syncthreads();
        const int d = tid >> 1, sh = tid & 1;
        const int head = bn >> 7;
        const float bv = bias[bn + d];
        #pragma unroll
        for (int s8 = 0; s8 < 8; s8++) {
            const int sl = sh * 64 + s8 * 8;
            union { bf16 b[8]; uint4 u; } hh, ll;
            #pragma unroll
            for (int u = 0; u < 8; u++) {
                float v = (ep[(sl + u) * 132 + d] + bv) * scale;
                hh.b[u] = __float2bfloat16(v);
                ll.b[u] = __float2bfloat16(v - __bfloat162float(hh.b[u]));
            }
            size_t base = ((size_t)head * HD + d) * SQ + bm + sl;
            *(uint4*)&Cb[base]  = hh.u;
            *(uint4*)&Cb2[base] = ll.u;
        }
    }
}

// ---------------- tensor-core flash attention --------------------------------
#define AS_Q    0
#define AS_K    51200
#define AS_PH   88064
#define AS_PL   122880
#define AS_VH   157696
#define AS_VL   192512
#define AS_REDM 227328
#define AS_REDL 228352
#define AS_ROWM 229376
#define AS_ROWC 229888
#define AS_ROWL 230400
#define ATTN_SMEM 230912

__device__ __forceinline__ float expapx(float x)
{
    if (x > -0.0625f)
        return 1.0f + x * (1.0f + x * (0.5f + x * 0.16666667f));
    return __expf(x);
}

__global__ __launch_bounds__(256) void attn4(
    const bf16* __restrict__ Qg, const bf16* __restrict__ Kg,
    const bf16* __restrict__ VTh, const bf16* __restrict__ VTl,
    bf16* __restrict__ Ctxh, bf16* __restrict__ Ctxl)
{
    extern __shared__ char sm[];
    const uint32_t sb = smem_u32(sm);
    float* redM = (float*)(sm + AS_REDM);
    float* redL = (float*)(sm + AS_REDL);
    float* rowM = (float*)(sm + AS_ROWM);
    float* rowC = (float*)(sm + AS_ROWC);
    float* rowL = (float*)(sm + AS_ROWL);

    const int qb = blockIdx.x, hh = blockIdx.y;
    const int tid = threadIdx.x;
    const int lane = tid & 31, wid = tid >> 5;
    const int g = lane >> 2, tig = lane & 3;
    const int wm = wid & 3, wn = wid >> 2;

    const bf16* Qh = Qg + ((size_t)hh * SQ + qb * 128) * DTOT;
    const bf16* Kh = Kg + (size_t)hh * SQ * DTOT;

    // Q -> smem once (stride 400 B)
    #pragma unroll
    for (int i = 0; i < 12; i++) {
        int id = tid + i * 256;
        int r = id / 24, c8 = id % 24;
        *(uint4*)(sm + AS_Q + r * 400 + c8 * 16) =
            *(const uint4*)(Qh + (size_t)r * DTOT + c8 * 8);
    }
    if (tid < 128) { rowM[tid] = -INFINITY; rowL[tid] = 0.0f; }

    float O[2][8][4] = {};

    const uint32_t aQ0 = sb + AS_Q + (wm * 32 + (lane & 15)) * 400 + ((lane >> 4) << 4);
    const uint32_t bK0 = (uint32_t)((wn * 64 + (lane & 7) + ((lane >> 4) << 3)) * 144
                                    + (((lane >> 3) & 1) << 4));
    const uint32_t aP0 = sb + AS_PH + (wm * 32 + (lane & 15)) * 272 + ((lane >> 4) << 4);
    const uint32_t bV0 = sb + AS_VH + (wn * 64 + (lane & 7) + ((lane >> 4) << 3)) * 272
                         + (((lane >> 3) & 1) << 4);

#define ISSUE_K(tile, kc) do { \
    int _buf = ((tile) * 3 + (kc)) & 1; \
    _Pragma("unroll") \
    for (int _i = 0; _i < 4; _i++) { \
        int _id = tid + _i * 256; \
        int _r = _id >> 3, _seg = _id & 7; \
        cp16(sb + AS_K + _buf * 18432 + _r * 144 + _seg * 16, \
             Kh + (size_t)((tile) * 128 + _r) * DTOT + (kc) * 64 + _seg * 8); \
    } \
} while (0)

#define ISSUE_V(tile) do { \
    _Pragma("unroll") \
    for (int _i = 0; _i < 16; _i++) { \
        int _id = tid + _i * 256; \
        int _mat = _id >> 11, _rid = _id & 2047; \
        int _r = _rid >> 4, _seg = _rid & 15; \
        const bf16* _src = (_mat ? VTl : VTh) \
            + ((size_t)hh * HD + _r) * SQ + (tile) * 128 + _seg * 8; \
        cp16(sb + (_mat ? AS_VL : AS_VH) + _r * 272 + _seg * 16, _src); \
    } \
} while (0)

#define QK_CHUNK(kc, buf) do { \
    const uint32_t _bK = sb + AS_K + (buf) * 18432 + bK0; \
    _Pragma("unroll") \
    for (int _ks = 0; _ks < 4; _ks++) { \
        const uint32_t _o = _ks * 32; \
        uint32_t _a[2][4], _b[4][4]; \
        ldsm4(_a[0], aQ0 + (kc) * 128 + _o); \
        ldsm4(_a[1], aQ0 + (kc) * 128 + 6400 + _o); \
        _Pragma("unroll") \
        for (int _jp = 0; _jp < 4; _jp++) ldsm4(_b[_jp], _bK + _jp * 2304 + _o); \
        _Pragma("unroll") \
        for (int _mt = 0; _mt < 2; _mt++) \
            _Pragma("unroll") \
            for (int _jp = 0; _jp < 4; _jp++) { \
                mma_bf16(S[_mt][2*_jp],   _a[_mt], &_b[_jp][0]); \
                mma_bf16(S[_mt][2*_jp+1], _a[_mt], &_b[_jp][2]); \
            } \
    } \
} while (0)

    // prologue: K chunk (0,0)
    ISSUE_K(0, 0);
    CP_COMMIT();

    for (int kb = 0; kb < SQ / 128; kb++) {
        const int g3 = kb * 3;
        ISSUE_V(kb);
        CP_COMMIT();

        float S[2][8][4] = {};
        // kc = 0
        ISSUE_K(kb, 1);
        CP_COMMIT();
        CP_WAIT(2);
        __syncthreads();
        QK_CHUNK(0, g3 & 1);
        __syncthreads();
        // kc = 1
        ISSUE_K(kb, 2);
        CP_COMMIT();
        CP_WAIT(1);
        __syncthreads();
        QK_CHUNK(1, (g3 + 1) & 1);
        __syncthreads();
        // kc = 2 (+ prefetch next tile's K0 during compute/softmax/PV)
        CP_WAIT(0);
        __syncthreads();
        if (kb + 1 < SQ / 128) {
            ISSUE_K(kb + 1, 0);
            CP_COMMIT();
        }
        QK_CHUNK(2, (g3 + 2) & 1);

        // ---- softmax ----
        #pragma unroll
        for (int mt = 0; mt < 2; mt++) {
            float m0 = -INFINITY, m1 = -INFINITY;
            #pragma unroll
            for (int j = 0; j < 8; j++) {
                m0 = fmaxf(m0, fmaxf(S[mt][j][0], S[mt][j][1]));
                m1 = fmaxf(m1, fmaxf(S[mt][j][2], S[mt][j][3]));
            }
            m0 = fmaxf(m0, __shfl_xor_sync(~0u, m0, 1));
            m0 = fmaxf(m0, __shfl_xor_sync(~0u, m0, 2));
            m1 = fmaxf(m1, __shfl_xor_sync(~0u, m1, 1));
            m1 = fmaxf(m1, __shfl_xor_sync(~0u, m1, 2));
            if (tig == 0) {
                redM[(wm * 32 + mt * 16 + g) * 2 + wn] = m0;
                redM[(wm * 32 + mt * 16 + g + 8) * 2 + wn] = m1;
            }
        }
        __syncthreads();
        if (wn == 0 && tig == 0) {
            #pragma unroll
            for (int mt = 0; mt < 2; mt++)
                #pragma unroll
                for (int hf = 0; hf < 2; hf++) {
                    int r = wm * 32 + mt * 16 + hf * 8 + g;
                    float tm = fmaxf(redM[r * 2], redM[r * 2 + 1]);
                    float mo = rowM[r];
                    float mn = fmaxf(mo, tm);
                    rowM[r] = mn;
                    rowC[r] = __expf(mo - mn);
                }
        }
        __syncthreads();

        #pragma unroll
        for (int mt = 0; mt < 2; mt++) {
            const int r0 = wm * 32 + mt * 16 + g, r1 = r0 + 8;
            const float mn0 = rowM[r0], mn1 = rowM[r1];
            const float c0 = rowC[r0], c1 = rowC[r1];
            float s0 = 0.0f, s1 = 0.0f;
            #pragma unroll
            for (int j = 0; j < 8; j++) {
                const int col = wn * 64 + j * 8 + tig * 2;
                float p00 = expapx(S[mt][j][0] - mn0);
                float p01 = expapx(S[mt][j][1] - mn0);
                float p10 = expapx(S[mt][j][2] - mn1);
                float p11 = expapx(S[mt][j][3] - mn1);
                s0 += p00 + p01;
                s1 += p10 + p11;
                BF2 h0, l0, h1, l1;
                h0.v = __floats2bfloat162_rn(p00, p01);
                float2 hf0 = __bfloat1622float2(h0.v);
                l0.v = __floats2bfloat162_rn(p00 - hf0.x, p01 - hf0.y);
                h1.v = __floats2bfloat162_rn(p10, p11);
                float2 hf1 = __bfloat1622float2(h1.v);
                l1.v = __floats2bfloat162_rn(p10 - hf1.x, p11 - hf1.y);
                *(uint32_t*)(sm + AS_PH + r0 * 272 + col * 2) = h0.u;
                *(uint32_t*)(sm + AS_PL + r0 * 272 + col * 2) = l0.u;
                *(uint32_t*)(sm + AS_PH + r1 * 272 + col * 2) = h1.u;
                *(uint32_t*)(sm + AS_PL + r1 * 272 + col * 2) = l1.u;
                O[mt][j][0] *= c0; O[mt][j][1] *= c0;
                O[mt][j][2] *= c1; O[mt][j][3] *= c1;
            }
            s0 += __shfl_xor_sync(~0u, s0, 1);
            s0 += __shfl_xor_sync(~0u, s0, 2);
            s1 += __shfl_xor_sync(~0u, s1, 1);
            s1 += __shfl_xor_sync(~0u, s1, 2);
            if (tig == 0) { redL[r0 * 2 + wn] = s0; redL[r1 * 2 + wn] = s1; }
        }
        __syncthreads();
        if (wn == 0 && tig == 0) {
            #pragma unroll
            for (int mt = 0; mt < 2; mt++)
                #pragma unroll
                for (int hf = 0; hf < 2; hf++) {
                    int r = wm * 32 + mt * 16 + hf * 8 + g;
                    rowL[r] = rowL[r] * rowC[r] + redL[r * 2] + redL[r * 2 + 1];
                }
        }

        // ---- O += P V  (V resident since kc=1 wait) ----
        #pragma unroll
        for (int ks = 0; ks < 8; ks++) {
            const uint32_t o = ks * 32;
            uint32_t ah[2][4], al[2][4], bh[4][4], bl[4][4];
            ldsm4(ah[0], aP0 + o);
            ldsm4(ah[1], aP0 + 4352 + o);
            ldsm4(al[0], aP0 + 34816 + o);
            ldsm4(al[1], aP0 + 34816 + 4352 + o);
            #pragma unroll
            for (int jp = 0; jp < 4; jp++) {
                ldsm4(bh[jp], bV0 + jp * 4352 + o);
                ldsm4(bl[jp], bV0 + 34816 + jp * 4352 + o);
            }
            #pragma unroll
            for (int mt = 0; mt < 2; mt++)
                #pragma unroll
                for (int jp = 0; jp < 4; jp++) {
                    mma_bf16(O[mt][2*jp],   ah[mt], &bh[jp][0]);
                    mma_bf16(O[mt][2*jp],   al[mt], &bh[jp][0]);
                    mma_bf16(O[mt][2*jp],   ah[mt], &bl[jp][0]);
                    mma_bf16(O[mt][2*jp+1], ah[mt], &bh[jp][2]);
                    mma_bf16(O[mt][2*jp+1], al[mt], &bh[jp][2]);
                    mma_bf16(O[mt][2*jp+1], ah[mt], &bl[jp][2]);
                }
        }
        __syncthreads();
    }
#undef ISSUE_K
#undef ISSUE_V
#undef QK_CHUNK

    // ---- finalize: ctx -> bf16 hi/lo ----
    #pragma unroll
    for (int mt = 0; mt < 2; mt++) {
        const int r0 = wm * 32 + mt * 16 + g, r1 = r0 + 8;
        const float i0 = 1.0f / rowL[r0], i1 = 1.0f / rowL[r1];
        const int q0 = qb * 128 + r0, q1 = qb * 128 + r1;
        #pragma unroll
        for (int j = 0; j < 8; j++) {
            const int col = hh * HD + wn * 64 + j * 8 + tig * 2;
            float v0x = O[mt][j][0] * i0, v0y = O[mt][j][1] * i0;
            float v1x = O[mt][j][2] * i1, v1y = O[mt][j][3] * i1;
            BF2 h0, l0, h1, l1;
            h0.v = __floats2bfloat162_rn(v0x, v0y);
            float2 f0 = __bfloat1622float2(h0.v);
            l0.v = __floats2bfloat162_rn(v0x - f0.x, v0y - f0.y);
            h1.v = __floats2bfloat162_rn(v1x, v1y);
            float2 f1 = __bfloat1622float2(h1.v);
            l1.v = __floats2bfloat162_rn(v1x - f1.x, v1y - f1.y);
            *(uint32_t*)&Ctxh[(size_t)q0 * (NH * HD) + col] = h0.u;
            *(uint32_t*)&Ctxl[(size_t)q0 * (NH * HD) + col] = l0.u;
            *(uint32_t*)&Ctxh[(size_t)q1 * (NH * HD) + col] = h1.u;
            *(uint32_t*)&Ctxl[(size_t)q1 * (NH * HD) + col] = l1.u;
        }
    }
}

// ---------------- launch ------------------------------------------------------
extern "C" void kernel_launch(void* const* d_in, const int* in_sizes, int n_in,
                              void* d_out, int out_size)
{
    const float* x   = (const float*)d_in[0];
    const float* kdw = (const float*)d_in[1];
    const float* kdb = (const float*)d_in[2];
    const float* kuw = (const float*)d_in[3];
    const float* kub = (const float*)d_in[4];
    const float* vuw = (const float*)d_in[5];
    const float* vub = (const float*)d_in[6];
    const float* krw = (const float*)d_in[7];
    const float* krb = (const float*)d_in[8];
    const float* qdw = (const float*)d_in[9];
    const float* qdb = (const float*)d_in[10];
    const float* quw = (const float*)d_in[11];
    const float* qub = (const float*)d_in[12];
    const float* qrw = (const float*)d_in[13];
    const float* qrb = (const float*)d_in[14];
    const float* ow  = (const float*)d_in[15];
    const float* ob  = (const float*)d_in[16];
    float* out = (float*)d_out;

#define SYM(p, s) cudaGetSymbolAddress((void**)&p, s)
    bf16 *xh, *xl, *kdwh, *kdwl, *qdwh, *kuwh, *vuwh, *vuwl, *quwh, *owh, *owl;
    bf16 *krwh, *qrwh, *kvch, *kvcl, *qch, *qhp, *khp, *vth, *vtl, *ctxh, *ctxl;
    float *krb2, *qrb2;
    SYM(xh, g_xh); SYM(xl, g_xl);
    SYM(kdwh, g_kdwh); SYM(kdwl, g_kdwl);
    SYM(qdwh, g_qdwh);
    SYM(kuwh, g_kuwh);
    SYM(vuwh, g_vuwh); SYM(vuwl, g_vuwl);
    SYM(quwh, g_quwh);
    SYM(owh, g_owh); SYM(owl, g_owl);
    SYM(krwh, g_krwh); SYM(qrwh, g_qrwh);
    SYM(kvch, g_kvch); SYM(kvcl, g_kvcl);
    SYM(qch, g_qch);
    SYM(qhp, g_qh); SYM(khp, g_kh);
    SYM(vth, g_vth); SYM(vtl, g_vtl);
    SYM(ctxh, g_ctxh); SYM(ctxl, g_ctxl);
    SYM(krb2, g_krb2); SYM(qrb2, g_qrb2);
#undef SYM

    const float scale = 1.0f / sqrtf((float)DTOT);
    cudaFuncSetAttribute(gemm_seg, cudaFuncAttributeMaxDynamicSharedMemorySize, GT_SMEM);
    cudaFuncSetAttribute(attn4, cudaFuncAttributeMaxDynamicSharedMemorySize, ATTN_SMEM);
    dim3 blk(256);

    // fused splits
    {
        STab t;
        t.j[0] = { x,   xh,   xl,   0 };
        t.j[1] = { kdw, kdwh, kdwl, 4096 };
        t.j[2] = { qdw, qdwh, 0,    5120 };
        t.j[3] = { kuw, kuwh, 0,    7168 };
        t.j[4] = { vuw, vuwh, vuwl, 8192 };
        t.j[5] = { quw, quwh, 0,    9216 };
        t.j[6] = { ow,  owh,  owl,  11264 };
        split_seg<<<15360, blk>>>(t);
    }
    rotate_split<<<dim3(2, NH * RD / 2), blk>>>(krw, krb, krwh, krb2, KVC);
    rotate_split<<<dim3(4, NH * RD / 2), blk>>>(qrw, qrb, qrwh, qrb2, QC);

    GSeg z = {};
    // L1: down projections (fused)
    {
        GTab t; t.nseg = 2;
        t.s[0] = { xh, xl, kdwh, kdwl, kdb, 0, kvch, kvcl, HID, 0, 0, KVC, 0, 1.0f, 3, 3, 0 };
        t.s[1] = { xh, 0,  qdwh, 0,    qdb, 0, qch,  0,    HID, 0, 0, QC,  0, 1.0f, 3, 1, 4 };
        t.s[2] = z; t.s[3] = z; t.s[4] = z;
        gemm_seg<<<dim3(12, 16), blk, GT_SMEM>>>(t);
    }
    // L2: up projections (fused)
    {
        GTab t; t.nseg = 5;
        t.s[0] = { kvch, 0,    kuwh, 0,    kub,  0, khp, 0,   KVC, HD, SQ*DTOT, DTOT, 0,  1.0f,  1, 1, 0 };
        t.s[1] = { kvch, 0,    krwh, 0,    krb2, 0, khp, 0,   KVC, RD, SQ*DTOT, DTOT, HD, 1.0f,  1, 1, 16 };
        t.s[2] = { kvch, kvcl, vuwh, vuwl, vub,  0, vth, vtl, KVC, 0,  0,       0,    0,  1.0f,  2, 3, 24 };
        t.s[3] = { qch,  0,    quwh, 0,    qub,  0, qhp, 0,   QC,  HD, SQ*DTOT, DTOT, 0,  scale, 1, 1, 40 };
        t.s[4] = { qch,  0,    qrwh, 0,    qrb2, 0, qhp, 0,   QC,  RD, SQ*DTOT, DTOT, HD, scale, 1, 1, 56 };
        gemm_seg<<<dim3(64, 16), blk, GT_SMEM>>>(t);
    }
    // attention
    attn4<<<dim3(SQ / 128, NH), blk, ATTN_SMEM>>>(qhp, khp, vth, vtl, ctxh, ctxl);
    // L4: output projection
    {
        GTab t; t.nseg = 1;
        t.s[0] = { ctxh, ctxl, owh, owl, ob, out, 0, 0, 2048, 2048, 0, 2048, 0, 1.0f, 0, 3, 0 };
        t.s[1] = z; t.s[2] = z; t.s[3] = z; t.s[4] = z;
        gemm_seg<<<dim3(16, 16), blk, GT_SMEM>>>(t);
    }
}

// round 8
// speedup vs baseline: 8.1403x; 1.0479x over previous
#include <cuda_runtime.h>
#include <cuda_bf16.h>
#include <math.h>
#include <stdint.h>

#define SQ   2048
#define HID  2048
#define NH   16
#define HD   128
#define RD   64
#define DTOT 192
#define KVC  512
#define QC   1024

typedef __nv_bfloat16 bf16;

// ---------------- scratch ----------------------------------------------------
__device__ bf16 g_xh[SQ * HID],      g_xl[SQ * HID];
__device__ bf16 g_kdwh[KVC * HID],   g_kdwl[KVC * HID];
__device__ bf16 g_qdwh[QC * HID];
__device__ bf16 g_kuwh[NH*HD*KVC];
__device__ bf16 g_vuwh[NH*HD*KVC],   g_vuwl[NH*HD*KVC];
__device__ bf16 g_quwh[NH*HD*QC];
__device__ bf16 g_owh[HID*NH*HD],    g_owl[HID*NH*HD];
__device__ bf16 g_krwh[NH*RD*KVC];
__device__ bf16 g_qrwh[NH*RD*QC];
__device__ float g_krb2[NH*RD], g_qrb2[NH*RD];
__device__ bf16 g_kvch[SQ*KVC],      g_kvcl[SQ*KVC];
__device__ bf16 g_qch[SQ*QC];
__device__ bf16 g_qh[NH*SQ*DTOT];
__device__ bf16 g_kh[NH*SQ*DTOT];
__device__ bf16 g_vth[NH*HD*SQ],     g_vtl[NH*HD*SQ];
__device__ bf16 g_ctxh[SQ*NH*HD],    g_ctxl[SQ*NH*HD];

// ---------------- helpers ----------------------------------------------------
union BF2 { __nv_bfloat162 v; uint32_t u; };

__device__ __forceinline__ uint32_t smem_u32(const void* p) {
    uint32_t a;
    asm("{ .reg .u64 t; cvta.to.shared.u64 t, %1; cvt.u32.u64 %0, t; }"
        : "=r"(a) : "l"(p));
    return a;
}
__device__ __forceinline__ void mma_bf16(float* c, const uint32_t* a, const uint32_t* b)
{
    asm volatile(
        "mma.sync.aligned.m16n8k16.row.col.f32.bf16.bf16.f32 "
        "{%0,%1,%2,%3}, {%4,%5,%6,%7}, {%8,%9}, {%0,%1,%2,%3};"
        : "+f"(c[0]), "+f"(c[1]), "+f"(c[2]), "+f"(c[3])
        : "r"(a[0]), "r"(a[1]), "r"(a[2]), "r"(a[3]), "r"(b[0]), "r"(b[1]));
}
__device__ __forceinline__ void ldsm4(uint32_t* r, uint32_t a) {
    asm volatile("ldmatrix.sync.aligned.m8n8.x4.shared.b16 {%0,%1,%2,%3}, [%4];"
        : "=r"(r[0]), "=r"(r[1]), "=r"(r[2]), "=r"(r[3]) : "r"(a));
}
__device__ __forceinline__ void cp16(uint32_t d, const void* s) {
    asm volatile("cp.async.cg.shared.global [%0], [%1], 16;" :: "r"(d), "l"(s));
}
#define CP_COMMIT() asm volatile("cp.async.commit_group;" ::: "memory")
#define CP_WAIT(n)  asm volatile("cp.async.wait_group %0;" :: "n"(n) : "memory")

// ---------------- fused splits ------------------------------------------------
struct SJob { const float* X; bf16* H; bf16* L; int b0; };
struct STab { SJob j[7]; };

__global__ void split_seg(STab t)
{
    int ji = 0;
    #pragma unroll
    for (int i = 1; i < 7; i++)
        if ((int)blockIdx.x >= t.j[i].b0) ji = i;
    const float* X = t.j[ji].X;
    bf16* H = t.j[ji].H;
    bf16* L = t.j[ji].L;
    int i = ((int)blockIdx.x - t.j[ji].b0) * 256 + threadIdx.x;
    float4 f = ((const float4*)X)[i];
    BF2 h0, h1;
    h0.v = __floats2bfloat162_rn(f.x, f.y);
    h1.v = __floats2bfloat162_rn(f.z, f.w);
    ((uint2*)H)[i] = make_uint2(h0.u, h1.u);
    if (L) {
        float2 g0 = __bfloat1622float2(h0.v), g1 = __bfloat1622float2(h1.v);
        BF2 l0, l1;
        l0.v = __floats2bfloat162_rn(f.x - g0.x, f.y - g0.y);
        l1.v = __floats2bfloat162_rn(f.z - g1.x, f.w - g1.y);
        ((uint2*)L)[i] = make_uint2(l0.u, l1.u);
    }
}

__global__ void rotate_split(const float* __restrict__ W, const float* __restrict__ b,
                             bf16* __restrict__ Wh, float* __restrict__ bo, int K)
{
    int pair = blockIdx.y;
    int h = pair >> 5;
    int i = pair & 31;
    float inv = powf(10000.0f, -(2.0f * (float)i) / 64.0f);
    float ang = (float)h * inv;
    float c = cosf(ang), s = sinf(ang);
    int c0 = pair * 2;
    int idx = blockIdx.x * 256 + threadIdx.x;
    if (idx < K) {
        float w1 = W[(size_t)c0 * K + idx];
        float w2 = W[(size_t)(c0 + 1) * K + idx];
        Wh[(size_t)c0 * K + idx]       = __float2bfloat16(c * w1 - s * w2);
        Wh[(size_t)(c0 + 1) * K + idx] = __float2bfloat16(s * w1 + c * w2);
    }
    if (idx == 0 && blockIdx.x == 0) {
        float b1 = b[c0], b2 = b[c0 + 1];
        bo[c0]     = c * b1 - s * b2;
        bo[c0 + 1] = s * b1 + c * b2;
    }
}

// ---------------- segmented tensor GEMM (chunk 64, 2-stage) -------------------
// modes: 0 fp32 scatter; 1 bf16 scatter; 2 V transpose hi/lo; 3 bf16 rows hi(+lo).
#define GST   144                 // bytes per row (64 bf16 + 16B pad)
#define GMATB (128 * GST)         // 18432
#define GT_SMEM (2 * 4 * GMATB)   // 147456 (np3, 2 stages)
#define GT_SMEM1 (2 * 2 * GMATB)  // 73728 (np1, 2 stages)

struct GSeg {
    const bf16 *Ah, *Al, *Bh, *Bl;
    const float* bias;
    float* C; bf16 *Cb; bf16 *Cb2;
    int K, head_sz, head_stride, row_stride, col_off;
    float scale;
    int mode, npass, bn0;
};
struct GTab { GSeg s[5]; int nseg; };

__global__ __launch_bounds__(256, 2) void gemm_seg(GTab tab)
{
    extern __shared__ char smem[];
    const uint32_t sb = smem_u32(smem);
    int si = 0;
    #pragma unroll
    for (int i = 1; i < 5; i++)
        if (i < tab.nseg && (int)blockIdx.x >= tab.s[i].bn0) si = i;
    const bf16* Ah = tab.s[si].Ah;
    const bf16* Al = tab.s[si].Al;
    const bf16* Bh = tab.s[si].Bh;
    const bf16* Bl = tab.s[si].Bl;
    const float* bias = tab.s[si].bias;
    const int K = tab.s[si].K;
    const int mode = tab.s[si].mode;
    const bool np3 = (tab.s[si].npass == 3);
    const int bn = ((int)blockIdx.x - tab.s[si].bn0) * 128;
    const int bm = blockIdx.y * 128;

    const int tid = threadIdx.x, lane = tid & 31, wid = tid >> 5;
    const int g = lane >> 2, tig = lane & 3;
    const int wm = wid & 3, wn = wid >> 2;

    const bf16* a0 = Ah + (size_t)bm * K;
    const bf16* a1 = np3 ? Al + (size_t)bm * K : a0;
    const bf16* b0 = Bh + (size_t)bn * K;
    const bf16* b1 = np3 ? Bl + (size_t)bn * K : b0;

    const uint32_t ssz = np3 ? 4 * GMATB : 2 * GMATB;
    const uint32_t bmat = np3 ? 2 * GMATB : GMATB;

    float acc[2][8][4] = {};

#define G_ISSUE(c, st) do { \
    uint32_t _base = sb + (st) * ssz; \
    if (np3) { \
        _Pragma("unroll") \
        for (int _i = 0; _i < 16; _i++) { \
            int _id = tid + (_i << 8); \
            int _mat = _id >> 10, _rid = _id & 1023; \
            int _row = _rid >> 3, _seg = _rid & 7; \
            const bf16* _mp = (_mat == 0) ? a0 : (_mat == 1) ? a1 : (_mat == 2) ? b0 : b1; \
            cp16(_base + _mat * GMATB + _row * GST + _seg * 16, \
                 _mp + (size_t)_row * K + (c) * 64 + _seg * 8); \
        } \
    } else { \
        _Pragma("unroll") \
        for (int _i = 0; _i < 8; _i++) { \
            int _id = tid + (_i << 8); \
            int _mat = _id >> 10, _rid = _id & 1023; \
            int _row = _rid >> 3, _seg = _rid & 7; \
            const bf16* _mp = (_mat == 0) ? a0 : b0; \
            cp16(_base + _mat * GMATB + _row * GST + _seg * 16, \
                 _mp + (size_t)_row * K + (c) * 64 + _seg * 8); \
        } \
    } \
} while (0)

    const uint32_t aoff = (uint32_t)((wm * 32 + (lane & 15)) * GST + ((lane >> 4) << 4));
    const uint32_t boff = (uint32_t)(bmat
        + (wn * 64 + (lane & 7) + ((lane >> 4) << 3)) * GST + (((lane >> 3) & 1) << 4));

    const int nch = K >> 6;
    G_ISSUE(0, 0);
    CP_COMMIT();
    for (int c = 0; c < nch; c++) {
        if (c + 1 < nch) { G_ISSUE(c + 1, (c + 1) & 1); CP_COMMIT(); CP_WAIT(1); }
        else CP_WAIT(0);
        __syncthreads();
        const uint32_t aA = sb + (c & 1) * ssz + aoff;
        const uint32_t bB = sb + (c & 1) * ssz + boff;
        #pragma unroll
        for (int ks = 0; ks < 4; ks++) {
            const uint32_t o = ks * 32;
            uint32_t ah[2][4], bh[4][4];
            ldsm4(ah[0], aA + o);
            ldsm4(ah[1], aA + 2304 + o);
            #pragma unroll
            for (int jp = 0; jp < 4; jp++) ldsm4(bh[jp], bB + jp * 2304 + o);
            if (np3) {
                uint32_t al[2][4], bl[4][4];
                ldsm4(al[0], aA + GMATB + o);
                ldsm4(al[1], aA + GMATB + 2304 + o);
                #pragma unroll
                for (int jp = 0; jp < 4; jp++) ldsm4(bl[jp], bB + GMATB + jp * 2304 + o);
                // pass 1: hi*hi (16 independent accumulators)
                #pragma unroll
                for (int mt = 0; mt < 2; mt++)
                    #pragma unroll
                    for (int jp = 0; jp < 4; jp++) {
                        mma_bf16(acc[mt][2*jp],   ah[mt], &bh[jp][0]);
                        mma_bf16(acc[mt][2*jp+1], ah[mt], &bh[jp][2]);
                    }
                // pass 2: lo*hi
                #pragma unroll
                for (int mt = 0; mt < 2; mt++)
                    #pragma unroll
                    for (int jp = 0; jp < 4; jp++) {
                        mma_bf16(acc[mt][2*jp],   al[mt], &bh[jp][0]);
                        mma_bf16(acc[mt][2*jp+1], al[mt], &bh[jp][2]);
                    }
                // pass 3: hi*lo
                #pragma unroll
                for (int mt = 0; mt < 2; mt++)
                    #pragma unroll
                    for (int jp = 0; jp < 4; jp++) {
                        mma_bf16(acc[mt][2*jp],   ah[mt], &bl[jp][0]);
                        mma_bf16(acc[mt][2*jp+1], ah[mt], &bl[jp][2]);
                    }
            } else {
                #pragma unroll
                for (int mt = 0; mt < 2; mt++)
                    #pragma unroll
                    for (int jp = 0; jp < 4; jp++) {
                        mma_bf16(acc[mt][2*jp],   ah[mt], &bh[jp][0]);
                        mma_bf16(acc[mt][2*jp+1], ah[mt], &bh[jp][2]);
                    }
            }
        }
        __syncthreads();
    }
#undef G_ISSUE

    const float scale = tab.s[si].scale;
    if (mode == 0 || mode == 1) {
        const int head_sz = tab.s[si].head_sz;
        const int head_stride = tab.s[si].head_stride;
        const int row_stride = tab.s[si].row_stride;
        const int col_off = tab.s[si].col_off;
        float* C = tab.s[si].C;
        bf16* Cb = tab.s[si].Cb;
        #pragma unroll
        for (int mt = 0; mt < 2; mt++) {
            const int row_lo = bm + wm * 32 + mt * 16 + g;
            const int row_hi = row_lo + 8;
            #pragma unroll
            for (int j = 0; j < 8; j++) {
                const int col = bn + wn * 64 + j * 8 + tig * 2;
                float2 bv = *(const float2*)(bias + col);
                const int dst0 = (col / head_sz) * head_stride + col_off + (col % head_sz);
                float v0x = (acc[mt][j][0] + bv.x) * scale;
                float v0y = (acc[mt][j][1] + bv.y) * scale;
                float v1x = (acc[mt][j][2] + bv.x) * scale;
                float v1y = (acc[mt][j][3] + bv.y) * scale;
                if (mode == 0) {
                    *(float2*)&C[(size_t)row_lo * row_stride + dst0] = make_float2(v0x, v0y);
                    *(float2*)&C[(size_t)row_hi * row_stride + dst0] = make_float2(v1x, v1y);
                } else {
                    BF2 t0, t1;
                    t0.v = __floats2bfloat162_rn(v0x, v0y);
                    t1.v = __floats2bfloat162_rn(v1x, v1y);
                    *(uint32_t*)&Cb[(size_t)row_lo * row_stride + dst0] = t0.u;
                    *(uint32_t*)&Cb[(size_t)row_hi * row_stride + dst0] = t1.u;
                }
            }
        }
    } else if (mode == 3) {
        const int row_stride = tab.s[si].row_stride;
        bf16* Cb = tab.s[si].Cb;
        bf16* Cb2 = tab.s[si].Cb2;
        #pragma unroll
        for (int mt = 0; mt < 2; mt++) {
            const int row_lo = bm + wm * 32 + mt * 16 + g;
            const int row_hi = row_lo + 8;
            #pragma unroll
            for (int j = 0; j < 8; j++) {
                const int col = bn + wn * 64 + j * 8 + tig * 2;
                float2 bv = *(const float2*)(bias + col);
                float v0x = (acc[mt][j][0] + bv.x) * scale;
                float v0y = (acc[mt][j][1] + bv.y) * scale;
                float v1x = (acc[mt][j][2] + bv.x) * scale;
                float v1y = (acc[mt][j][3] + bv.y) * scale;
                BF2 h0, h1;
                h0.v = __floats2bfloat162_rn(v0x, v0y);
                h1.v = __floats2bfloat162_rn(v1x, v1y);
                *(uint32_t*)&Cb[(size_t)row_lo * row_stride + col] = h0.u;
                *(uint32_t*)&Cb[(size_t)row_hi * row_stride + col] = h1.u;
                if (Cb2) {
                    float2 g0 = __bfloat1622float2(h0.v), g1 = __bfloat1622float2(h1.v);
                    BF2 l0, l1;
                    l0.v = __floats2bfloat162_rn(v0x - g0.x, v0y - g0.y);
                    l1.v = __floats2bfloat162_rn(v1x - g1.x, v1y - g1.y);
                    *(uint32_t*)&Cb2[(size_t)row_lo * row_stride + col] = l0.u;
                    *(uint32_t*)&Cb2[(size_t)row_hi * row_stride + col] = l1.u;
                }
            }
        }
    } else {
        bf16* Cb = tab.s[si].Cb;
        bf16* Cb2 = tab.s[si].Cb2;
        float* ep = (float*)smem;
        #pragma unroll
        for (int mt = 0; mt < 2; mt++) {
            const int r0 = wm * 32 + mt * 16 + g;
            #pragma unroll
            for (int j = 0; j < 8; j++) {
                const int cl = wn * 64 + j * 8 + tig * 2;
                *(float2*)&ep[r0 * 132 + cl]       = make_float2(acc[mt][j][0], acc[mt][j][1]);
                *(float2*)&ep[(r0 + 8) * 132 + cl] = make_float2(acc[mt][j][2], acc[mt][j][3]);
            }
        }
        __syncthreads();
        const int d = tid >> 1, sh = tid & 1;
        const int head = bn >> 7;
        const float bv = bias[bn + d];
        #pragma unroll
        for (int s8 = 0; s8 < 8; s8++) {
            const int sl = sh * 64 + s8 * 8;
            union { bf16 b[8]; uint4 u; } hh, ll;
            #pragma unroll
            for (int u = 0; u < 8; u++) {
                float v = (ep[(sl + u) * 132 + d] + bv) * scale;
                hh.b[u] = __float2bfloat16(v);
                ll.b[u] = __float2bfloat16(v - __bfloat162float(hh.b[u]));
            }
            size_t base = ((size_t)head * HD + d) * SQ + bm + sl;
            *(uint4*)&Cb[base]  = hh.u;
            *(uint4*)&Cb2[base] = ll.u;
        }
    }
}

// ---------------- tensor-core flash attention --------------------------------
#define AS_Q    0
#define AS_K    51200
#define AS_PH   88064
#define AS_PL   122880
#define AS_VH   157696
#define AS_VL   192512
#define AS_REDM 227328
#define AS_REDL 228352
#define AS_ROWM 229376
#define AS_ROWC 229888
#define AS_ROWL 230400
#define ATTN_SMEM 230912

__device__ __forceinline__ float expapx(float x)
{
    if (x > -0.0625f)
        return 1.0f + x * (1.0f + x * (0.5f + x * 0.16666667f));
    return __expf(x);
}

__global__ __launch_bounds__(256) void attn4(
    const bf16* __restrict__ Qg, const bf16* __restrict__ Kg,
    const bf16* __restrict__ VTh, const bf16* __restrict__ VTl,
    bf16* __restrict__ Ctxh, bf16* __restrict__ Ctxl)
{
    extern __shared__ char sm[];
    const uint32_t sb = smem_u32(sm);
    float* redM = (float*)(sm + AS_REDM);
    float* redL = (float*)(sm + AS_REDL);
    float* rowM = (float*)(sm + AS_ROWM);
    float* rowC = (float*)(sm + AS_ROWC);
    float* rowL = (float*)(sm + AS_ROWL);

    const int qb = blockIdx.x, hh = blockIdx.y;
    const int tid = threadIdx.x;
    const int lane = tid & 31, wid = tid >> 5;
    const int g = lane >> 2, tig = lane & 3;
    const int wm = wid & 3, wn = wid >> 2;

    const bf16* Qh = Qg + ((size_t)hh * SQ + qb * 128) * DTOT;
    const bf16* Kh = Kg + (size_t)hh * SQ * DTOT;

    #pragma unroll
    for (int i = 0; i < 12; i++) {
        int id = tid + i * 256;
        int r = id / 24, c8 = id % 24;
        *(uint4*)(sm + AS_Q + r * 400 + c8 * 16) =
            *(const uint4*)(Qh + (size_t)r * DTOT + c8 * 8);
    }
    if (tid < 128) { rowM[tid] = -INFINITY; rowL[tid] = 0.0f; }

    float O[2][8][4] = {};

    const uint32_t aQ0 = sb + AS_Q + (wm * 32 + (lane & 15)) * 400 + ((lane >> 4) << 4);
    const uint32_t bK0 = (uint32_t)((wn * 64 + (lane & 7) + ((lane >> 4) << 3)) * 144
                                    + (((lane >> 3) & 1) << 4));
    const uint32_t aP0 = sb + AS_PH + (wm * 32 + (lane & 15)) * 272 + ((lane >> 4) << 4);
    const uint32_t bV0 = sb + AS_VH + (wn * 64 + (lane & 7) + ((lane >> 4) << 3)) * 272
                         + (((lane >> 3) & 1) << 4);

#define ISSUE_K(tile, kc) do { \
    int _buf = ((tile) * 3 + (kc)) & 1; \
    _Pragma("unroll") \
    for (int _i = 0; _i < 4; _i++) { \
        int _id = tid + _i * 256; \
        int _r = _id >> 3, _seg = _id & 7; \
        cp16(sb + AS_K + _buf * 18432 + _r * 144 + _seg * 16, \
             Kh + (size_t)((tile) * 128 + _r) * DTOT + (kc) * 64 + _seg * 8); \
    } \
} while (0)

#define ISSUE_V(tile) do { \
    _Pragma("unroll") \
    for (int _i = 0; _i < 16; _i++) { \
        int _id = tid + _i * 256; \
        int _mat = _id >> 11, _rid = _id & 2047; \
        int _r = _rid >> 4, _seg = _rid & 15; \
        const bf16* _src = (_mat ? VTl : VTh) \
            + ((size_t)hh * HD + _r) * SQ + (tile) * 128 + _seg * 8; \
        cp16(sb + (_mat ? AS_VL : AS_VH) + _r * 272 + _seg * 16, _src); \
    } \
} while (0)

#define QK_CHUNK(kc, buf) do { \
    const uint32_t _bK = sb + AS_K + (buf) * 18432 + bK0; \
    _Pragma("unroll") \
    for (int _ks = 0; _ks < 4; _ks++) { \
        const uint32_t _o = _ks * 32; \
        uint32_t _a[2][4], _b[4][4]; \
        ldsm4(_a[0], aQ0 + (kc) * 128 + _o); \
        ldsm4(_a[1], aQ0 + (kc) * 128 + 6400 + _o); \
        _Pragma("unroll") \
        for (int _jp = 0; _jp < 4; _jp++) ldsm4(_b[_jp], _bK + _jp * 2304 + _o); \
        _Pragma("unroll") \
        for (int _mt = 0; _mt < 2; _mt++) \
            _Pragma("unroll") \
            for (int _jp = 0; _jp < 4; _jp++) { \
                mma_bf16(S[_mt][2*_jp],   _a[_mt], &_b[_jp][0]); \
                mma_bf16(S[_mt][2*_jp+1], _a[_mt], &_b[_jp][2]); \
            } \
    } \
} while (0)

    ISSUE_K(0, 0);
    CP_COMMIT();

    for (int kb = 0; kb < SQ / 128; kb++) {
        const int g3 = kb * 3;
        ISSUE_V(kb);
        CP_COMMIT();

        float S[2][8][4] = {};
        ISSUE_K(kb, 1);
        CP_COMMIT();
        CP_WAIT(2);
        __syncthreads();
        QK_CHUNK(0, g3 & 1);
        __syncthreads();
        ISSUE_K(kb, 2);
        CP_COMMIT();
        CP_WAIT(1);
        __syncthreads();
        QK_CHUNK(1, (g3 + 1) & 1);
        __syncthreads();
        CP_WAIT(0);
        __syncthreads();
        if (kb + 1 < SQ / 128) {
            ISSUE_K(kb + 1, 0);
            CP_COMMIT();
        }
        QK_CHUNK(2, (g3 + 2) & 1);

        // ---- softmax ----
        #pragma unroll
        for (int mt = 0; mt < 2; mt++) {
            float m0 = -INFINITY, m1 = -INFINITY;
            #pragma unroll
            for (int j = 0; j < 8; j++) {
                m0 = fmaxf(m0, fmaxf(S[mt][j][0], S[mt][j][1]));
                m1 = fmaxf(m1, fmaxf(S[mt][j][2], S[mt][j][3]));
            }
            m0 = fmaxf(m0, __shfl_xor_sync(~0u, m0, 1));
            m0 = fmaxf(m0, __shfl_xor_sync(~0u, m0, 2));
            m1 = fmaxf(m1, __shfl_xor_sync(~0u, m1, 1));
            m1 = fmaxf(m1, __shfl_xor_sync(~0u, m1, 2));
            if (tig == 0) {
                redM[(wm * 32 + mt * 16 + g) * 2 + wn] = m0;
                redM[(wm * 32 + mt * 16 + g + 8) * 2 + wn] = m1;
            }
        }
        __syncthreads();
        if (wn == 0 && tig == 0) {
            #pragma unroll
            for (int mt = 0; mt < 2; mt++)
                #pragma unroll
                for (int hf = 0; hf < 2; hf++) {
                    int r = wm * 32 + mt * 16 + hf * 8 + g;
                    float tm = fmaxf(redM[r * 2], redM[r * 2 + 1]);
                    float mo = rowM[r];
                    float mn = fmaxf(mo, tm);
                    rowM[r] = mn;
                    rowC[r] = __expf(mo - mn);
                }
        }
        __syncthreads();

        #pragma unroll
        for (int mt = 0; mt < 2; mt++) {
            const int r0 = wm * 32 + mt * 16 + g, r1 = r0 + 8;
            const float mn0 = rowM[r0], mn1 = rowM[r1];
            const float c0 = rowC[r0], c1 = rowC[r1];
            float s0 = 0.0f, s1 = 0.0f;
            #pragma unroll
            for (int j = 0; j < 8; j++) {
                const int col = wn * 64 + j * 8 + tig * 2;
                float p00 = expapx(S[mt][j][0] - mn0);
                float p01 = expapx(S[mt][j][1] - mn0);
                float p10 = expapx(S[mt][j][2] - mn1);
                float p11 = expapx(S[mt][j][3] - mn1);
                s0 += p00 + p01;
                s1 += p10 + p11;
                BF2 h0, l0, h1, l1;
                h0.v = __floats2bfloat162_rn(p00, p01);
                float2 hf0 = __bfloat1622float2(h0.v);
                l0.v = __floats2bfloat162_rn(p00 - hf0.x, p01 - hf0.y);
                h1.v = __floats2bfloat162_rn(p10, p11);
                float2 hf1 = __bfloat1622float2(h1.v);
                l1.v = __floats2bfloat162_rn(p10 - hf1.x, p11 - hf1.y);
                *(uint32_t*)(sm + AS_PH + r0 * 272 + col * 2) = h0.u;
                *(uint32_t*)(sm + AS_PL + r0 * 272 + col * 2) = l0.u;
                *(uint32_t*)(sm + AS_PH + r1 * 272 + col * 2) = h1.u;
                *(uint32_t*)(sm + AS_PL + r1 * 272 + col * 2) = l1.u;
                O[mt][j][0] *= c0; O[mt][j][1] *= c0;
                O[mt][j][2] *= c1; O[mt][j][3] *= c1;
            }
            s0 += __shfl_xor_sync(~0u, s0, 1);
            s0 += __shfl_xor_sync(~0u, s0, 2);
            s1 += __shfl_xor_sync(~0u, s1, 1);
            s1 += __shfl_xor_sync(~0u, s1, 2);
            if (tig == 0) { redL[r0 * 2 + wn] = s0; redL[r1 * 2 + wn] = s1; }
        }
        __syncthreads();
        if (wn == 0 && tig == 0) {
            #pragma unroll
            for (int mt = 0; mt < 2; mt++)
                #pragma unroll
                for (int hf = 0; hf < 2; hf++) {
                    int r = wm * 32 + mt * 16 + hf * 8 + g;
                    rowL[r] = rowL[r] * rowC[r] + redL[r * 2] + redL[r * 2 + 1];
                }
        }

        // ---- O += P V  (pass-separated) ----
        #pragma unroll
        for (int ks = 0; ks < 8; ks++) {
            const uint32_t o = ks * 32;
            uint32_t ah[2][4], al[2][4], bh[4][4], bl[4][4];
            ldsm4(ah[0], aP0 + o);
            ldsm4(ah[1], aP0 + 4352 + o);
            ldsm4(al[0], aP0 + 34816 + o);
            ldsm4(al[1], aP0 + 34816 + 4352 + o);
            #pragma unroll
            for (int jp = 0; jp < 4; jp++) {
                ldsm4(bh[jp], bV0 + jp * 4352 + o);
                ldsm4(bl[jp], bV0 + 34816 + jp * 4352 + o);
            }
            #pragma unroll
            for (int mt = 0; mt < 2; mt++)
                #pragma unroll
                for (int jp = 0; jp < 4; jp++) {
                    mma_bf16(O[mt][2*jp],   ah[mt], &bh[jp][0]);
                    mma_bf16(O[mt][2*jp+1], ah[mt], &bh[jp][2]);
                }
            #pragma unroll
            for (int mt = 0; mt < 2; mt++)
                #pragma unroll
                for (int jp = 0; jp < 4; jp++) {
                    mma_bf16(O[mt][2*jp],   al[mt], &bh[jp][0]);
                    mma_bf16(O[mt][2*jp+1], al[mt], &bh[jp][2]);
                }
            #pragma unroll
            for (int mt = 0; mt < 2; mt++)
                #pragma unroll
                for (int jp = 0; jp < 4; jp++) {
                    mma_bf16(O[mt][2*jp],   ah[mt], &bl[jp][0]);
                    mma_bf16(O[mt][2*jp+1], ah[mt], &bl[jp][2]);
                }
        }
        __syncthreads();
    }
#undef ISSUE_K
#undef ISSUE_V
#undef QK_CHUNK

    #pragma unroll
    for (int mt = 0; mt < 2; mt++) {
        const int r0 = wm * 32 + mt * 16 + g, r1 = r0 + 8;
        const float i0 = 1.0f / rowL[r0], i1 = 1.0f / rowL[r1];
        const int q0 = qb * 128 + r0, q1 = qb * 128 + r1;
        #pragma unroll
        for (int j = 0; j < 8; j++) {
            const int col = hh * HD + wn * 64 + j * 8 + tig * 2;
            float v0x = O[mt][j][0] * i0, v0y = O[mt][j][1] * i0;
            float v1x = O[mt][j][2] * i1, v1y = O[mt][j][3] * i1;
            BF2 h0, l0, h1, l1;
            h0.v = __floats2bfloat162_rn(v0x, v0y);
            float2 f0 = __bfloat1622float2(h0.v);
            l0.v = __floats2bfloat162_rn(v0x - f0.x, v0y - f0.y);
            h1.v = __floats2bfloat162_rn(v1x, v1y);
            float2 f1 = __bfloat1622float2(h1.v);
            l1.v = __floats2bfloat162_rn(v1x - f1.x, v1y - f1.y);
            *(uint32_t*)&Ctxh[(size_t)q0 * (NH * HD) + col] = h0.u;
            *(uint32_t*)&Ctxl[(size_t)q0 * (NH * HD) + col] = l0.u;
            *(uint32_t*)&Ctxh[(size_t)q1 * (NH * HD) + col] = h1.u;
            *(uint32_t*)&Ctxl[(size_t)q1 * (NH * HD) + col] = l1.u;
        }
    }
}

// ---------------- launch ------------------------------------------------------
extern "C" void kernel_launch(void* const* d_in, const int* in_sizes, int n_in,
                              void* d_out, int out_size)
{
    const float* x   = (const float*)d_in[0];
    const float* kdw = (const float*)d_in[1];
    const float* kdb = (const float*)d_in[2];
    const float* kuw = (const float*)d_in[3];
    const float* kub = (const float*)d_in[4];
    const float* vuw = (const float*)d_in[5];
    const float* vub = (const float*)d_in[6];
    const float* krw = (const float*)d_in[7];
    const float* krb = (const float*)d_in[8];
    const float* qdw = (const float*)d_in[9];
    const float* qdb = (const float*)d_in[10];
    const float* quw = (const float*)d_in[11];
    const float* qub = (const float*)d_in[12];
    const float* qrw = (const float*)d_in[13];
    const float* qrb = (const float*)d_in[14];
    const float* ow  = (const float*)d_in[15];
    const float* ob  = (const float*)d_in[16];
    float* out = (float*)d_out;

#define SYM(p, s) cudaGetSymbolAddress((void**)&p, s)
    bf16 *xh, *xl, *kdwh, *kdwl, *qdwh, *kuwh, *vuwh, *vuwl, *quwh, *owh, *owl;
    bf16 *krwh, *qrwh, *kvch, *kvcl, *qch, *qhp, *khp, *vth, *vtl, *ctxh, *ctxl;
    float *krb2, *qrb2;
    SYM(xh, g_xh); SYM(xl, g_xl);
    SYM(kdwh, g_kdwh); SYM(kdwl, g_kdwl);
    SYM(qdwh, g_qdwh);
    SYM(kuwh, g_kuwh);
    SYM(vuwh, g_vuwh); SYM(vuwl, g_vuwl);
    SYM(quwh, g_quwh);
    SYM(owh, g_owh); SYM(owl, g_owl);
    SYM(krwh, g_krwh); SYM(qrwh, g_qrwh);
    SYM(kvch, g_kvch); SYM(kvcl, g_kvcl);
    SYM(qch, g_qch);
    SYM(qhp, g_qh); SYM(khp, g_kh);
    SYM(vth, g_vth); SYM(vtl, g_vtl);
    SYM(ctxh, g_ctxh); SYM(ctxl, g_ctxl);
    SYM(krb2, g_krb2); SYM(qrb2, g_qrb2);
#undef SYM

    const float scale = 1.0f / sqrtf((float)DTOT);
    cudaFuncSetAttribute(gemm_seg, cudaFuncAttributeMaxDynamicSharedMemorySize, GT_SMEM);
    cudaFuncSetAttribute(attn4, cudaFuncAttributeMaxDynamicSharedMemorySize, ATTN_SMEM);
    dim3 blk(256);

    {
        STab t;
        t.j[0] = { x,   xh,   xl,   0 };
        t.j[1] = { kdw, kdwh, kdwl, 4096 };
        t.j[2] = { qdw, qdwh, 0,    5120 };
        t.j[3] = { kuw, kuwh, 0,    7168 };
        t.j[4] = { vuw, vuwh, vuwl, 8192 };
        t.j[5] = { quw, quwh, 0,    9216 };
        t.j[6] = { ow,  owh,  owl,  11264 };
        split_seg<<<15360, blk>>>(t);
    }
    rotate_split<<<dim3(2, NH * RD / 2), blk>>>(krw, krb, krwh, krb2, KVC);
    rotate_split<<<dim3(4, NH * RD / 2), blk>>>(qrw, qrb, qrwh, qrb2, QC);

    GSeg z = {};
    // L1: down projections (kv np3 + q np1)
    {
        GTab t; t.nseg = 2;
        t.s[0] = { xh, xl, kdwh, kdwl, kdb, 0, kvch, kvcl, HID, 0, 0, KVC, 0, 1.0f, 3, 3, 0 };
        t.s[1] = { xh, 0,  qdwh, 0,    qdb, 0, qch,  0,    HID, 0, 0, QC,  0, 1.0f, 3, 1, 4 };
        t.s[2] = z; t.s[3] = z; t.s[4] = z;
        gemm_seg<<<dim3(12, 16), blk, GT_SMEM>>>(t);
    }
    // L2a: np1 up projections (2 CTAs/SM)
    {
        GTab t; t.nseg = 4;
        t.s[0] = { kvch, 0, kuwh, 0, kub,  0, khp, 0, KVC, HD, SQ*DTOT, DTOT, 0,  1.0f,  1, 1, 0 };
        t.s[1] = { kvch, 0, krwh, 0, krb2, 0, khp, 0, KVC, RD, SQ*DTOT, DTOT, HD, 1.0f,  1, 1, 16 };
        t.s[2] = { qch,  0, quwh, 0, qub,  0, qhp, 0, QC,  HD, SQ*DTOT, DTOT, 0,  scale, 1, 1, 24 };
        t.s[3] = { qch,  0, qrwh, 0, qrb2, 0, qhp, 0, QC,  RD, SQ*DTOT, DTOT, HD, scale, 1, 1, 40 };
        t.s[4] = z;
        gemm_seg<<<dim3(48, 16), blk, GT_SMEM1>>>(t);
    }
    // L2b: v_up (np3, transpose)
    {
        GTab t; t.nseg = 1;
        t.s[0] = { kvch, kvcl, vuwh, vuwl, vub, 0, vth, vtl, KVC, 0, 0, 0, 0, 1.0f, 2, 3, 0 };
        t.s[1] = z; t.s[2] = z; t.s[3] = z; t.s[4] = z;
        gemm_seg<<<dim3(16, 16), blk, GT_SMEM>>>(t);
    }
    // attention
    attn4<<<dim3(SQ / 128, NH), blk, ATTN_SMEM>>>(qhp, khp, vth, vtl, ctxh, ctxl);
    // L4: output projection
    {
        GTab t; t.nseg = 1;
        t.s[0] = { ctxh, ctxl, owh, owl, ob, out, 0, 0, 2048, 2048, 0, 2048, 0, 1.0f, 0, 3, 0 };
        t.s[1] = z; t.s[2] = z; t.s[3] = z; t.s[4] = z;
        gemm_seg<<<dim3(16, 16), blk, GT_SMEM>>>(t);
    }
}